// round 1
// baseline (speedup 1.0000x reference)
#include <cuda_runtime.h>
#include <cuda_bf16.h>
#include <cstddef>
#include <math.h>

// Problem constants
#define BB 2
#define NN_SEQ 2048
#define DD 1024
#define HH 16
#define HD 64
#define ROWS (BB * NN_SEQ)          // 4096
#define EHALF (BB * HH * NN_SEQ * HD) // 4194304

// ---------------- scratch (device globals; no allocation allowed) ----------
__device__ float g_qkv[ROWS * 3 * DD];     // 4096 x 3072
__device__ float g_q[EHALF];               // [B,H,N,HD]
__device__ float g_k[EHALF];
__device__ float g_v[EHALF];
__device__ float g_ctx[ROWS * DD];         // [B,N,D]
__device__ float g_msg[ROWS * DD];
__device__ float g_cat[ROWS * 2 * DD];     // 4096 x 2048
__device__ float g_h[ROWS * 2 * DD];       // 4096 x 2048

// ---------------- generic fp32 GEMM:  C[M,Nn] = A[M,K] @ W[Nn,K]^T + bias (+res)
__global__ void __launch_bounds__(256) gemm_kernel(
    const float* __restrict__ A, const float* __restrict__ W,
    const float* __restrict__ bias, const float* __restrict__ res,
    float* __restrict__ C, int M, int Nn, int K)
{
    __shared__ __align__(16) float As[16][68];
    __shared__ __align__(16) float Bs[16][68];
    const int tid = threadIdx.x;
    const int tx = tid & 15, ty = tid >> 4;
    const int m0 = blockIdx.y * 64, n0 = blockIdx.x * 64;
    const float* Ab = A + (size_t)m0 * K;
    const float* Wb = W + (size_t)n0 * K;

    float acc[4][4];
#pragma unroll
    for (int i = 0; i < 4; i++)
#pragma unroll
        for (int j = 0; j < 4; j++) acc[i][j] = 0.f;

    for (int k0 = 0; k0 < K; k0 += 16) {
#pragma unroll
        for (int i = 0; i < 4; i++) {
            int idx = tid + i * 256;       // 0..1023 : 64 rows x 16 k
            int r = idx >> 4, kk = idx & 15;
            As[kk][r] = Ab[(size_t)r * K + k0 + kk];
            Bs[kk][r] = Wb[(size_t)r * K + k0 + kk];
        }
        __syncthreads();
#pragma unroll
        for (int kk = 0; kk < 16; kk++) {
            float a[4], b[4];
            *(float4*)a = *(const float4*)&As[kk][ty * 4];
            *(float4*)b = *(const float4*)&Bs[kk][tx * 4];
#pragma unroll
            for (int i = 0; i < 4; i++)
#pragma unroll
                for (int j = 0; j < 4; j++)
                    acc[i][j] += a[i] * b[j];
        }
        __syncthreads();
    }

#pragma unroll
    for (int i = 0; i < 4; i++) {
        int m = m0 + ty * 4 + i;
#pragma unroll
        for (int j = 0; j < 4; j++) {
            int n = n0 + tx * 4 + j;
            float v = acc[i][j] + bias[n];
            if (res) v += res[(size_t)m * Nn + n];
            C[(size_t)m * Nn + n] = v;
        }
    }
}

// ---------------- rope + deinterleave qkv -> q,k,v [B,H,N,HD] --------------
__global__ void __launch_bounds__(256) rope_scatter_kernel(
    const float* __restrict__ qkv, const float* __restrict__ enc,
    float* __restrict__ q, float* __restrict__ k, float* __restrict__ v)
{
    int idx = blockIdx.x * 256 + threadIdx.x;   // linear over [B,H,N,HD]
    if (idx >= EHALF) return;
    int d = idx & 63;
    int n = (idx >> 6) & (NN_SEQ - 1);
    int h = (idx >> 17) & 15;
    int b = idx >> 21;

    size_t row = (size_t)(b * NN_SEQ + n) * (3 * DD);
    int col  = (h * HD + d) * 3;
    int dp   = d ^ 1;
    int colp = (h * HD + dp) * 3;

    float e0 = enc[idx];
    float e1 = enc[EHALF + idx];

    float qr = qkv[row + col];
    float kr = qkv[row + col + 1];
    float vr = qkv[row + col + 2];
    float qp = qkv[row + colp];
    float kp = qkv[row + colp + 1];

    float sgn = (d & 1) ? 1.f : -1.f;   // even d: -x[d+1]; odd d: +x[d-1]
    q[idx] = qr * e0 + sgn * qp * e1;
    k[idx] = kr * e0 + sgn * kp * e1;
    v[idx] = vr;
}

// ---------------- flash-style attention, fp32 ------------------------------
// grid: (N/64, B*H); block 256. Writes context directly in [B,N,D] layout.
__global__ void __launch_bounds__(256) attn_kernel(
    const float* __restrict__ Qg, const float* __restrict__ Kg,
    const float* __restrict__ Vg, float* __restrict__ ctx)
{
    extern __shared__ __align__(16) float sm[];
    float* Qs = sm;             // [d][r]  64x64 (transposed)
    float* Ks = sm + 4096;      // [d][c]  64x64 (transposed)
    float* Vs = sm + 8192;      // [kv][hd] 64x64
    float* Ps = sm + 12288;     // [r][kv] 64x64

    const int tid = threadIdx.x;
    const int tx = tid & 15, ty = tid >> 4;
    const int bh = blockIdx.y;
    const int q0 = blockIdx.x * 64;
    const int b = bh >> 4, h = bh & 15;
    const float scale = 0.125f;   // 1/sqrt(64)

    const float* Qb = Qg + ((size_t)bh * NN_SEQ + q0) * HD;
    const float* Kb = Kg + (size_t)bh * NN_SEQ * HD;
    const float* Vb = Vg + (size_t)bh * NN_SEQ * HD;

    // load Q tile transposed (and pre-scaled)
#pragma unroll
    for (int i = 0; i < 4; i++) {
        int idx = tid + i * 256;       // r(0..63) x d4(0..15)
        int r = idx & 63, d4 = idx >> 6;
        float4 qv = *(const float4*)&Qb[r * HD + d4 * 4];
        Qs[(d4 * 4 + 0) * 64 + r] = qv.x * scale;
        Qs[(d4 * 4 + 1) * 64 + r] = qv.y * scale;
        Qs[(d4 * 4 + 2) * 64 + r] = qv.z * scale;
        Qs[(d4 * 4 + 3) * 64 + r] = qv.w * scale;
    }

    float m_i[4], l_i[4], o[4][4];
#pragma unroll
    for (int i = 0; i < 4; i++) {
        m_i[i] = -1e30f; l_i[i] = 0.f;
#pragma unroll
        for (int j = 0; j < 4; j++) o[i][j] = 0.f;
    }

    for (int kv0 = 0; kv0 < NN_SEQ; kv0 += 64) {
        __syncthreads();   // Qs ready / prev tile's Ps,Vs consumed
        // load K transposed, V direct
#pragma unroll
        for (int i = 0; i < 4; i++) {
            int idx = tid + i * 256;
            int r = idx & 63, d4 = idx >> 6;
            float4 kvv = *(const float4*)&Kb[(kv0 + r) * HD + d4 * 4];
            Ks[(d4 * 4 + 0) * 64 + r] = kvv.x;
            Ks[(d4 * 4 + 1) * 64 + r] = kvv.y;
            Ks[(d4 * 4 + 2) * 64 + r] = kvv.z;
            Ks[(d4 * 4 + 3) * 64 + r] = kvv.w;
            int rv = idx >> 4, c4 = idx & 15;
            *(float4*)&Vs[rv * 64 + c4 * 4] = *(const float4*)&Vb[(kv0 + rv) * HD + c4 * 4];
        }
        __syncthreads();

        // S = Q @ K^T (scaled)
        float s[4][4];
#pragma unroll
        for (int i = 0; i < 4; i++)
#pragma unroll
            for (int j = 0; j < 4; j++) s[i][j] = 0.f;
#pragma unroll 8
        for (int d = 0; d < 64; d++) {
            float a[4], bq[4];
            *(float4*)a  = *(const float4*)&Qs[d * 64 + ty * 4];
            *(float4*)bq = *(const float4*)&Ks[d * 64 + tx * 4];
#pragma unroll
            for (int i = 0; i < 4; i++)
#pragma unroll
                for (int j = 0; j < 4; j++)
                    s[i][j] += a[i] * bq[j];
        }

        // online softmax per row (rows shared across the 16 tx lanes)
#pragma unroll
        for (int i = 0; i < 4; i++) {
            float mx = fmaxf(fmaxf(s[i][0], s[i][1]), fmaxf(s[i][2], s[i][3]));
#pragma unroll
            for (int off = 8; off > 0; off >>= 1)
                mx = fmaxf(mx, __shfl_xor_sync(0xffffffffu, mx, off));
            float mn = fmaxf(m_i[i], mx);
            float alpha = __expf(m_i[i] - mn);
            m_i[i] = mn;
            l_i[i] *= alpha;
#pragma unroll
            for (int j = 0; j < 4; j++) o[i][j] *= alpha;
            float rs = 0.f;
#pragma unroll
            for (int j = 0; j < 4; j++) {
                float p = __expf(s[i][j] - mn);
                s[i][j] = p;
                rs += p;
            }
#pragma unroll
            for (int off = 8; off > 0; off >>= 1)
                rs += __shfl_xor_sync(0xffffffffu, rs, off);
            l_i[i] += rs;
            *(float4*)&Ps[(ty * 4 + i) * 64 + tx * 4] =
                make_float4(s[i][0], s[i][1], s[i][2], s[i][3]);
        }
        __syncthreads();

        // O += P @ V
#pragma unroll 4
        for (int kk = 0; kk < 64; kk += 4) {
            float p[4][4], vv[4][4];
#pragma unroll
            for (int i = 0; i < 4; i++)
                *(float4*)p[i] = *(const float4*)&Ps[(ty * 4 + i) * 64 + kk];
#pragma unroll
            for (int t = 0; t < 4; t++)
                *(float4*)vv[t] = *(const float4*)&Vs[(kk + t) * 64 + tx * 4];
#pragma unroll
            for (int i = 0; i < 4; i++)
#pragma unroll
                for (int j = 0; j < 4; j++)
                    o[i][j] += p[i][0] * vv[0][j] + p[i][1] * vv[1][j]
                             + p[i][2] * vv[2][j] + p[i][3] * vv[3][j];
        }
    }

    // epilogue: normalize and write context as [B,N,D]
#pragma unroll
    for (int i = 0; i < 4; i++) {
        float inv = 1.f / l_i[i];
        int n = q0 + ty * 4 + i;
        float* dst = ctx + ((size_t)b * NN_SEQ + n) * DD + h * HD + tx * 4;
        *(float4*)dst = make_float4(o[i][0] * inv, o[i][1] * inv,
                                    o[i][2] * inv, o[i][3] * inv);
    }
}

// ---------------- concat [descriptor | message] -> cat [4096, 2048] --------
__global__ void __launch_bounds__(256) concat_kernel(
    const float* __restrict__ desc, const float* __restrict__ msg,
    float* __restrict__ cat)
{
    int idx = blockIdx.x * 256 + threadIdx.x;   // float4 index over 4096*512
    int row = idx >> 9, c = idx & 511;
    float4 v = (c < 256)
        ? ((const float4*)desc)[(size_t)row * 256 + c]
        : ((const float4*)msg)[(size_t)row * 256 + (c - 256)];
    ((float4*)cat)[idx] = v;
}

// ---------------- LayerNorm + exact GELU (in place on g_h) -----------------
__global__ void __launch_bounds__(256) ln_gelu_kernel(
    float* __restrict__ H, const float* __restrict__ g, const float* __restrict__ bta)
{
    __shared__ float rs[8], rq[8], stat[2];
    float* hr = H + (size_t)blockIdx.x * 2048;
    const int tid = threadIdx.x;

    float4 x[2];
    float sum = 0.f, sq = 0.f;
#pragma unroll
    for (int t = 0; t < 2; t++) {
        x[t] = *(const float4*)&hr[(tid + t * 256) * 4];
        sum += x[t].x + x[t].y + x[t].z + x[t].w;
        sq  += x[t].x * x[t].x + x[t].y * x[t].y + x[t].z * x[t].z + x[t].w * x[t].w;
    }
#pragma unroll
    for (int off = 16; off > 0; off >>= 1) {
        sum += __shfl_xor_sync(0xffffffffu, sum, off);
        sq  += __shfl_xor_sync(0xffffffffu, sq,  off);
    }
    int w = tid >> 5, lane = tid & 31;
    if (!lane) { rs[w] = sum; rq[w] = sq; }
    __syncthreads();
    if (tid == 0) {
        float S = 0.f, Q = 0.f;
#pragma unroll
        for (int i = 0; i < 8; i++) { S += rs[i]; Q += rq[i]; }
        float mu = S * (1.f / 2048.f);
        float var = Q * (1.f / 2048.f) - mu * mu;
        stat[0] = mu;
        stat[1] = rsqrtf(var + 1e-5f);
    }
    __syncthreads();
    float mu = stat[0], rstd = stat[1];

#pragma unroll
    for (int t = 0; t < 2; t++) {
        int c0 = (tid + t * 256) * 4;
        float4 gg = *(const float4*)&g[c0];
        float4 bb = *(const float4*)&bta[c0];
        float xs[4] = {x[t].x, x[t].y, x[t].z, x[t].w};
        float gs[4] = {gg.x, gg.y, gg.z, gg.w};
        float bs[4] = {bb.x, bb.y, bb.z, bb.w};
        float ys[4];
#pragma unroll
        for (int j = 0; j < 4; j++) {
            float xn = (xs[j] - mu) * rstd * gs[j] + bs[j];
            ys[j] = 0.5f * xn * (1.f + erff(xn * 0.70710678118654752f));
        }
        *(float4*)&hr[c0] = make_float4(ys[0], ys[1], ys[2], ys[3]);
    }
}

// ---------------- launch ----------------------------------------------------
extern "C" void kernel_launch(void* const* d_in, const int* in_sizes, int n_in,
                              void* d_out, int out_size)
{
    const float* desc   = (const float*)d_in[0];
    const float* enc    = (const float*)d_in[1];
    const float* w_qkv  = (const float*)d_in[2];
    const float* b_qkv  = (const float*)d_in[3];
    const float* w_out  = (const float*)d_in[4];
    const float* b_out  = (const float*)d_in[5];
    const float* w_ffn1 = (const float*)d_in[6];
    const float* b_ffn1 = (const float*)d_in[7];
    const float* ln_g   = (const float*)d_in[8];
    const float* ln_b   = (const float*)d_in[9];
    const float* w_ffn2 = (const float*)d_in[10];
    const float* b_ffn2 = (const float*)d_in[11];
    float* out = (float*)d_out;

    float *p_qkv, *p_q, *p_k, *p_v, *p_ctx, *p_msg, *p_cat, *p_h;
    cudaGetSymbolAddress((void**)&p_qkv, g_qkv);
    cudaGetSymbolAddress((void**)&p_q,   g_q);
    cudaGetSymbolAddress((void**)&p_k,   g_k);
    cudaGetSymbolAddress((void**)&p_v,   g_v);
    cudaGetSymbolAddress((void**)&p_ctx, g_ctx);
    cudaGetSymbolAddress((void**)&p_msg, g_msg);
    cudaGetSymbolAddress((void**)&p_cat, g_cat);
    cudaGetSymbolAddress((void**)&p_h,   g_h);

    cudaFuncSetAttribute(attn_kernel, cudaFuncAttributeMaxDynamicSharedMemorySize, 65536);

    // 1. QKV projection: [4096,1024] @ [3072,1024]^T -> [4096,3072]
    gemm_kernel<<<dim3(3072 / 64, ROWS / 64), 256>>>(
        desc, w_qkv, b_qkv, nullptr, p_qkv, ROWS, 3072, 1024);

    // 2. rope + scatter to q,k,v [B,H,N,HD]
    rope_scatter_kernel<<<EHALF / 256, 256>>>(p_qkv, enc, p_q, p_k, p_v);

    // 3. attention -> ctx [B,N,D]
    attn_kernel<<<dim3(NN_SEQ / 64, BB * HH), 256, 65536>>>(p_q, p_k, p_v, p_ctx);

    // 4. output projection -> message
    gemm_kernel<<<dim3(1024 / 64, ROWS / 64), 256>>>(
        p_ctx, w_out, b_out, nullptr, p_msg, ROWS, 1024, 1024);

    // 5. concat [descriptor | message]
    concat_kernel<<<(ROWS * 512) / 256, 256>>>(desc, p_msg, p_cat);

    // 6. FFN1: [4096,2048] @ [2048,2048]^T
    gemm_kernel<<<dim3(2048 / 64, ROWS / 64), 256>>>(
        p_cat, w_ffn1, b_ffn1, nullptr, p_h, ROWS, 2048, 2048);

    // 7. LayerNorm + GELU in place
    ln_gelu_kernel<<<ROWS, 256>>>(p_h, ln_g, ln_b);

    // 8. FFN2 + residual -> out
    gemm_kernel<<<dim3(1024 / 64, ROWS / 64), 256>>>(
        p_h, w_ffn2, b_ffn2, desc, out, ROWS, 1024, 2048);
}

// round 3
// speedup vs baseline: 1.5757x; 1.5757x over previous
#include <cuda_runtime.h>
#include <cuda_bf16.h>
#include <cstdint>
#include <cstddef>
#include <math.h>

// Problem constants
#define BB 2
#define NN_SEQ 2048
#define DD 1024
#define HH 16
#define HD 64
#define ROWS (BB * NN_SEQ)            // 4096
#define EHALF (BB * HH * NN_SEQ * HD) // 4194304

// ---------------- scratch (device globals; no allocation allowed) ----------
__device__ float g_qkv[ROWS * 3 * DD];     // 4096 x 3072
__device__ float g_q[EHALF];               // [B,H,N,HD]
__device__ float g_k[EHALF];
__device__ float g_v[EHALF];
__device__ float g_ctx[ROWS * DD];         // [B,N,D]
__device__ float g_cat[ROWS * 2 * DD];     // 4096 x 2048 : [desc | message]
__device__ float g_h[ROWS * 2 * DD];       // 4096 x 2048

// ============================================================================
// helpers
// ============================================================================
__device__ __forceinline__ uint32_t smem_u32(const void* p) {
    uint32_t a;
    asm("{ .reg .u64 t; cvta.to.shared.u64 t, %1; cvt.u32.u64 %0, t; }"
        : "=r"(a) : "l"(p));
    return a;
}
__device__ __forceinline__ uint32_t sw128(uint32_t off) {
    return off ^ ((off >> 3) & 0x70);
}
// split a float into bf16 hi + bf16 lo  (x ~= hi + lo, |lo| <= 2^-9 |x|)
__device__ __forceinline__ void split2(float x0, float x1, uint32_t& hi, uint32_t& lo) {
    __nv_bfloat16 h0 = __float2bfloat16(x0);
    __nv_bfloat16 h1 = __float2bfloat16(x1);
    __nv_bfloat16 l0 = __float2bfloat16(x0 - __bfloat162float(h0));
    __nv_bfloat16 l1 = __float2bfloat16(x1 - __bfloat162float(h1));
    hi = (uint32_t)__bfloat16_as_ushort(h0) | ((uint32_t)__bfloat16_as_ushort(h1) << 16);
    lo = (uint32_t)__bfloat16_as_ushort(l0) | ((uint32_t)__bfloat16_as_ushort(l1) << 16);
}
__device__ __forceinline__ void ldsm4(uint32_t addr, uint32_t& r0, uint32_t& r1,
                                      uint32_t& r2, uint32_t& r3) {
    asm volatile("ldmatrix.sync.aligned.m8n8.x4.shared.b16 {%0,%1,%2,%3}, [%4];"
                 : "=r"(r0), "=r"(r1), "=r"(r2), "=r"(r3) : "r"(addr));
}
__device__ __forceinline__ void mma16816(float* c, uint32_t a0, uint32_t a1,
                                         uint32_t a2, uint32_t a3,
                                         uint32_t b0, uint32_t b1) {
    asm volatile(
        "mma.sync.aligned.m16n8k16.row.col.f32.bf16.bf16.f32 "
        "{%0,%1,%2,%3}, {%4,%5,%6,%7}, {%8,%9}, {%0,%1,%2,%3};"
        : "+f"(c[0]), "+f"(c[1]), "+f"(c[2]), "+f"(c[3])
        : "r"(a0), "r"(a1), "r"(a2), "r"(a3), "r"(b0), "r"(b1));
}

// ============================================================================
// HMMA split-bf16 GEMM:  C[M, n] = A[M,K] @ W[n,K]^T + bias (+res), fp32 I/O
// CTA tile 128x128, BK=32. grid (n/128, M/128), block 256 (8 warps, 2x4).
// SMEM row layout (128B): [32 hi bf16 | 32 lo bf16], SW128 swizzled.
// ============================================================================
__global__ void __launch_bounds__(256) gemm_tc(
    const float* __restrict__ A, const float* __restrict__ W,
    const float* __restrict__ bias, const float* __restrict__ res,
    float* __restrict__ C, int K, int ldc, int NC)
{
    __shared__ __align__(1024) char As[16384];
    __shared__ __align__(1024) char Bs[16384];
    const uint32_t as_base = smem_u32(As);
    const uint32_t bs_base = smem_u32(Bs);

    const int tid = threadIdx.x;
    const int lane = tid & 31, wid = tid >> 5;
    const int wm = wid >> 2, wn = wid & 3;    // warp grid 2(m) x 4(n)
    const int m0 = blockIdx.y * 128, n0 = blockIdx.x * 128;

    const float* Ab = A + (size_t)m0 * K;
    const float* Wb = W + (size_t)n0 * K;

    // STS mapping: f = tid + i*256 -> r = f>>3 (0..127), kq = f&7 (float4 idx)
    const int sr = tid >> 3, skq = tid & 7;

    // prefetch chunk 0
    float4 pa[4], pb[4];
#pragma unroll
    for (int i = 0; i < 4; i++) {
        int r = sr + i * 32;
        pa[i] = *(const float4*)&Ab[(size_t)r * K + skq * 4];
        pb[i] = *(const float4*)&Wb[(size_t)r * K + skq * 4];
    }

    float acc[4][4][4];
#pragma unroll
    for (int mt = 0; mt < 4; mt++)
#pragma unroll
        for (int nt = 0; nt < 4; nt++)
#pragma unroll
            for (int e = 0; e < 4; e++) acc[mt][nt][e] = 0.f;

    // per-lane ldmatrix geometry
    const int lrow = (lane & 7) + ((lane >> 3) & 1) * 8;   // row within 16-row tile
    const int lkh  = ((lane >> 4) & 1) * 8;                // k-half offset (0 / 8)

    for (int c = 0; c < NC; c++) {
        // ---- store current chunk (from prefetch regs) into SMEM, split hi/lo
#pragma unroll
        for (int i = 0; i < 4; i++) {
            int r = sr + i * 32;
            uint32_t off = (uint32_t)(r * 128 + skq * 8);
            uint32_t h0, l0, h1, l1;
            split2(pa[i].x, pa[i].y, h0, l0);
            split2(pa[i].z, pa[i].w, h1, l1);
            *(uint2*)(As + sw128(off))      = make_uint2(h0, h1);
            *(uint2*)(As + sw128(off + 64)) = make_uint2(l0, l1);
            split2(pb[i].x, pb[i].y, h0, l0);
            split2(pb[i].z, pb[i].w, h1, l1);
            *(uint2*)(Bs + sw128(off))      = make_uint2(h0, h1);
            *(uint2*)(Bs + sw128(off + 64)) = make_uint2(l0, l1);
        }
        __syncthreads();

        // ---- prefetch next chunk
        if (c + 1 < NC) {
            int kc = (c + 1) * 32;
#pragma unroll
            for (int i = 0; i < 4; i++) {
                int r = sr + i * 32;
                pa[i] = *(const float4*)&Ab[(size_t)r * K + kc + skq * 4];
                pb[i] = *(const float4*)&Wb[(size_t)r * K + kc + skq * 4];
            }
        }

        // ---- MMA: two k16 steps
#pragma unroll
        for (int s = 0; s < 2; s++) {
            const int kh = s * 16 + lkh;     // k-half index 0..31
            uint32_t ah[4][4], al[4][4];
#pragma unroll
            for (int mt = 0; mt < 4; mt++) {
                uint32_t row = (uint32_t)(wm * 64 + mt * 16 + lrow);
                uint32_t offh = row * 128 + kh * 2;
                ldsm4(as_base + sw128(offh),
                      ah[mt][0], ah[mt][1], ah[mt][2], ah[mt][3]);
                ldsm4(as_base + sw128(offh + 64),
                      al[mt][0], al[mt][1], al[mt][2], al[mt][3]);
            }
            uint32_t bh[2][4], bl[2][4];
#pragma unroll
            for (int p = 0; p < 2; p++) {
                uint32_t row = (uint32_t)(wn * 32 + p * 16 + lrow);
                uint32_t offh = row * 128 + kh * 2;
                ldsm4(bs_base + sw128(offh),
                      bh[p][0], bh[p][1], bh[p][2], bh[p][3]);
                ldsm4(bs_base + sw128(offh + 64),
                      bl[p][0], bl[p][1], bl[p][2], bl[p][3]);
            }
#pragma unroll
            for (int mt = 0; mt < 4; mt++) {
#pragma unroll
                for (int nt = 0; nt < 4; nt++) {
                    int p = nt >> 1, q = nt & 1;
                    // hi*hi
                    mma16816(acc[mt][nt], ah[mt][0], ah[mt][1], ah[mt][2], ah[mt][3],
                             bh[p][q], bh[p][q + 2]);
                    // hi*lo
                    mma16816(acc[mt][nt], ah[mt][0], ah[mt][1], ah[mt][2], ah[mt][3],
                             bl[p][q], bl[p][q + 2]);
                    // lo*hi
                    mma16816(acc[mt][nt], al[mt][0], al[mt][1], al[mt][2], al[mt][3],
                             bh[p][q], bh[p][q + 2]);
                }
            }
        }
        __syncthreads();
    }

    // ---- epilogue: store accumulators (+bias, +res) directly
    const int g = lane >> 2, tg = lane & 3;
#pragma unroll
    for (int mt = 0; mt < 4; mt++) {
#pragma unroll
        for (int nt = 0; nt < 4; nt++) {
            int row = m0 + wm * 64 + mt * 16 + g;
            int col = n0 + wn * 32 + nt * 8 + 2 * tg;
            float2 bv = *(const float2*)&bias[col];
            float2 v0 = make_float2(acc[mt][nt][0] + bv.x, acc[mt][nt][1] + bv.y);
            float2 v1 = make_float2(acc[mt][nt][2] + bv.x, acc[mt][nt][3] + bv.y);
            if (res) {
                float2 r0 = *(const float2*)&res[(size_t)row * ldc + col];
                float2 r1 = *(const float2*)&res[(size_t)(row + 8) * ldc + col];
                v0.x += r0.x; v0.y += r0.y; v1.x += r1.x; v1.y += r1.y;
            }
            *(float2*)&C[(size_t)row * ldc + col] = v0;
            *(float2*)&C[(size_t)(row + 8) * ldc + col] = v1;
        }
    }
}

// ---------------- rope + deinterleave qkv -> q,k,v [B,H,N,HD] --------------
__global__ void __launch_bounds__(256) rope_scatter_kernel(
    const float* __restrict__ qkv, const float* __restrict__ enc,
    float* __restrict__ q, float* __restrict__ k, float* __restrict__ v)
{
    int idx = blockIdx.x * 256 + threadIdx.x;
    if (idx >= EHALF) return;
    int d = idx & 63;
    int n = (idx >> 6) & (NN_SEQ - 1);
    int h = (idx >> 17) & 15;
    int b = idx >> 21;

    size_t row = (size_t)(b * NN_SEQ + n) * (3 * DD);
    int col  = (h * HD + d) * 3;
    int dp   = d ^ 1;
    int colp = (h * HD + dp) * 3;

    float e0 = enc[idx];
    float e1 = enc[EHALF + idx];

    float qr = qkv[row + col];
    float kr = qkv[row + col + 1];
    float vr = qkv[row + col + 2];
    float qp = qkv[row + colp];
    float kp = qkv[row + colp + 1];

    float sgn = (d & 1) ? 1.f : -1.f;
    q[idx] = qr * e0 + sgn * qp * e1;
    k[idx] = kr * e0 + sgn * kp * e1;
    v[idx] = vr;
}

// ---------------- flash-style attention, fp32 ------------------------------
__global__ void __launch_bounds__(256) attn_kernel(
    const float* __restrict__ Qg, const float* __restrict__ Kg,
    const float* __restrict__ Vg, float* __restrict__ ctx)
{
    extern __shared__ __align__(16) float sm[];
    float* Qs = sm;
    float* Ks = sm + 4096;
    float* Vs = sm + 8192;
    float* Ps = sm + 12288;

    const int tid = threadIdx.x;
    const int tx = tid & 15, ty = tid >> 4;
    const int bh = blockIdx.y;
    const int q0 = blockIdx.x * 64;
    const int b = bh >> 4, h = bh & 15;
    const float scale = 0.125f;

    const float* Qb = Qg + ((size_t)bh * NN_SEQ + q0) * HD;
    const float* Kb = Kg + (size_t)bh * NN_SEQ * HD;
    const float* Vb = Vg + (size_t)bh * NN_SEQ * HD;

#pragma unroll
    for (int i = 0; i < 4; i++) {
        int idx = tid + i * 256;
        int r = idx & 63, d4 = idx >> 6;
        float4 qv = *(const float4*)&Qb[r * HD + d4 * 4];
        Qs[(d4 * 4 + 0) * 64 + r] = qv.x * scale;
        Qs[(d4 * 4 + 1) * 64 + r] = qv.y * scale;
        Qs[(d4 * 4 + 2) * 64 + r] = qv.z * scale;
        Qs[(d4 * 4 + 3) * 64 + r] = qv.w * scale;
    }

    float m_i[4], l_i[4], o[4][4];
#pragma unroll
    for (int i = 0; i < 4; i++) {
        m_i[i] = -1e30f; l_i[i] = 0.f;
#pragma unroll
        for (int j = 0; j < 4; j++) o[i][j] = 0.f;
    }

    for (int kv0 = 0; kv0 < NN_SEQ; kv0 += 64) {
        __syncthreads();
#pragma unroll
        for (int i = 0; i < 4; i++) {
            int idx = tid + i * 256;
            int r = idx & 63, d4 = idx >> 6;
            float4 kvv = *(const float4*)&Kb[(kv0 + r) * HD + d4 * 4];
            Ks[(d4 * 4 + 0) * 64 + r] = kvv.x;
            Ks[(d4 * 4 + 1) * 64 + r] = kvv.y;
            Ks[(d4 * 4 + 2) * 64 + r] = kvv.z;
            Ks[(d4 * 4 + 3) * 64 + r] = kvv.w;
            int rv = idx >> 4, c4 = idx & 15;
            *(float4*)&Vs[rv * 64 + c4 * 4] = *(const float4*)&Vb[(kv0 + rv) * HD + c4 * 4];
        }
        __syncthreads();

        float s[4][4];
#pragma unroll
        for (int i = 0; i < 4; i++)
#pragma unroll
            for (int j = 0; j < 4; j++) s[i][j] = 0.f;
#pragma unroll 8
        for (int d = 0; d < 64; d++) {
            float a[4], bq[4];
            *(float4*)a  = *(const float4*)&Qs[d * 64 + ty * 4];
            *(float4*)bq = *(const float4*)&Ks[d * 64 + tx * 4];
#pragma unroll
            for (int i = 0; i < 4; i++)
#pragma unroll
                for (int j = 0; j < 4; j++)
                    s[i][j] += a[i] * bq[j];
        }

#pragma unroll
        for (int i = 0; i < 4; i++) {
            float mx = fmaxf(fmaxf(s[i][0], s[i][1]), fmaxf(s[i][2], s[i][3]));
#pragma unroll
            for (int off = 8; off > 0; off >>= 1)
                mx = fmaxf(mx, __shfl_xor_sync(0xffffffffu, mx, off));
            float mn = fmaxf(m_i[i], mx);
            float alpha = __expf(m_i[i] - mn);
            m_i[i] = mn;
            l_i[i] *= alpha;
#pragma unroll
            for (int j = 0; j < 4; j++) o[i][j] *= alpha;
            float rs = 0.f;
#pragma unroll
            for (int j = 0; j < 4; j++) {
                float p = __expf(s[i][j] - mn);
                s[i][j] = p;
                rs += p;
            }
#pragma unroll
            for (int off = 8; off > 0; off >>= 1)
                rs += __shfl_xor_sync(0xffffffffu, rs, off);
            l_i[i] += rs;
            *(float4*)&Ps[(ty * 4 + i) * 64 + tx * 4] =
                make_float4(s[i][0], s[i][1], s[i][2], s[i][3]);
        }
        __syncthreads();

#pragma unroll 4
        for (int kk = 0; kk < 64; kk += 4) {
            float p[4][4], vv[4][4];
#pragma unroll
            for (int i = 0; i < 4; i++)
                *(float4*)p[i] = *(const float4*)&Ps[(ty * 4 + i) * 64 + kk];
#pragma unroll
            for (int t = 0; t < 4; t++)
                *(float4*)vv[t] = *(const float4*)&Vs[(kk + t) * 64 + tx * 4];
#pragma unroll
            for (int i = 0; i < 4; i++)
#pragma unroll
                for (int j = 0; j < 4; j++)
                    o[i][j] += p[i][0] * vv[0][j] + p[i][1] * vv[1][j]
                             + p[i][2] * vv[2][j] + p[i][3] * vv[3][j];
        }
    }

#pragma unroll
    for (int i = 0; i < 4; i++) {
        float inv = 1.f / l_i[i];
        int n = q0 + ty * 4 + i;
        float* dst = ctx + ((size_t)b * NN_SEQ + n) * DD + h * HD + tx * 4;
        *(float4*)dst = make_float4(o[i][0] * inv, o[i][1] * inv,
                                    o[i][2] * inv, o[i][3] * inv);
    }
}

// ---------------- copy descriptor into first half of g_cat -----------------
__global__ void __launch_bounds__(256) desc_copy_kernel(
    const float* __restrict__ desc, float* __restrict__ cat)
{
    int idx = blockIdx.x * 256 + threadIdx.x;   // float4 over 4096*256
    int row = idx >> 8, c = idx & 255;
    ((float4*)cat)[(size_t)row * 512 + c] = ((const float4*)desc)[idx];
}

// ---------------- LayerNorm + exact GELU (in place on g_h) -----------------
__global__ void __launch_bounds__(256) ln_gelu_kernel(
    float* __restrict__ H, const float* __restrict__ g, const float* __restrict__ bta)
{
    __shared__ float rs[8], rq[8], stat[2];
    float* hr = H + (size_t)blockIdx.x * 2048;
    const int tid = threadIdx.x;

    float4 x[2];
    float sum = 0.f, sq = 0.f;
#pragma unroll
    for (int t = 0; t < 2; t++) {
        x[t] = *(const float4*)&hr[(tid + t * 256) * 4];
        sum += x[t].x + x[t].y + x[t].z + x[t].w;
        sq  += x[t].x * x[t].x + x[t].y * x[t].y + x[t].z * x[t].z + x[t].w * x[t].w;
    }
#pragma unroll
    for (int off = 16; off > 0; off >>= 1) {
        sum += __shfl_xor_sync(0xffffffffu, sum, off);
        sq  += __shfl_xor_sync(0xffffffffu, sq,  off);
    }
    int w = tid >> 5, lane = tid & 31;
    if (!lane) { rs[w] = sum; rq[w] = sq; }
    __syncthreads();
    if (tid == 0) {
        float S = 0.f, Q = 0.f;
#pragma unroll
        for (int i = 0; i < 8; i++) { S += rs[i]; Q += rq[i]; }
        float mu = S * (1.f / 2048.f);
        float var = Q * (1.f / 2048.f) - mu * mu;
        stat[0] = mu;
        stat[1] = rsqrtf(var + 1e-5f);
    }
    __syncthreads();
    float mu = stat[0], rstd = stat[1];

#pragma unroll
    for (int t = 0; t < 2; t++) {
        int c0 = (tid + t * 256) * 4;
        float4 gg = *(const float4*)&g[c0];
        float4 bb = *(const float4*)&bta[c0];
        float xs[4] = {x[t].x, x[t].y, x[t].z, x[t].w};
        float gs[4] = {gg.x, gg.y, gg.z, gg.w};
        float bs[4] = {bb.x, bb.y, bb.z, bb.w};
        float ys[4];
#pragma unroll
        for (int j = 0; j < 4; j++) {
            float xn = (xs[j] - mu) * rstd * gs[j] + bs[j];
            ys[j] = 0.5f * xn * (1.f + erff(xn * 0.70710678118654752f));
        }
        *(float4*)&hr[c0] = make_float4(ys[0], ys[1], ys[2], ys[3]);
    }
}

// ---------------- launch ----------------------------------------------------
extern "C" void kernel_launch(void* const* d_in, const int* in_sizes, int n_in,
                              void* d_out, int out_size)
{
    const float* desc   = (const float*)d_in[0];
    const float* enc    = (const float*)d_in[1];
    const float* w_qkv  = (const float*)d_in[2];
    const float* b_qkv  = (const float*)d_in[3];
    const float* w_out  = (const float*)d_in[4];
    const float* b_out  = (const float*)d_in[5];
    const float* w_ffn1 = (const float*)d_in[6];
    const float* b_ffn1 = (const float*)d_in[7];
    const float* ln_g   = (const float*)d_in[8];
    const float* ln_b   = (const float*)d_in[9];
    const float* w_ffn2 = (const float*)d_in[10];
    const float* b_ffn2 = (const float*)d_in[11];
    float* out = (float*)d_out;

    float *p_qkv, *p_q, *p_k, *p_v, *p_ctx, *p_cat, *p_h;
    cudaGetSymbolAddress((void**)&p_qkv, g_qkv);
    cudaGetSymbolAddress((void**)&p_q,   g_q);
    cudaGetSymbolAddress((void**)&p_k,   g_k);
    cudaGetSymbolAddress((void**)&p_v,   g_v);
    cudaGetSymbolAddress((void**)&p_ctx, g_ctx);
    cudaGetSymbolAddress((void**)&p_cat, g_cat);
    cudaGetSymbolAddress((void**)&p_h,   g_h);

    cudaFuncSetAttribute(attn_kernel, cudaFuncAttributeMaxDynamicSharedMemorySize, 65536);

    // 0. descriptor -> first half of concat buffer (independent)
    desc_copy_kernel<<<4096, 256>>>(desc, p_cat);

    // 1. QKV projection: [4096,1024] @ [3072,1024]^T -> [4096,3072]
    gemm_tc<<<dim3(3072 / 128, ROWS / 128), 256>>>(
        desc, w_qkv, b_qkv, nullptr, p_qkv, 1024, 3072, 32);

    // 2. rope + scatter
    rope_scatter_kernel<<<EHALF / 256, 256>>>(p_qkv, enc, p_q, p_k, p_v);

    // 3. attention -> ctx [B,N,D]
    attn_kernel<<<dim3(NN_SEQ / 64, BB * HH), 256, 65536>>>(p_q, p_k, p_v, p_ctx);

    // 4. output projection -> message (second half of g_cat, ldc=2048)
    gemm_tc<<<dim3(1024 / 128, ROWS / 128), 256>>>(
        p_ctx, w_out, b_out, nullptr, p_cat + 1024, 1024, 2048, 32);

    // 5. FFN1: [4096,2048] @ [2048,2048]^T
    gemm_tc<<<dim3(2048 / 128, ROWS / 128), 256>>>(
        p_cat, w_ffn1, b_ffn1, nullptr, p_h, 2048, 2048, 64);

    // 6. LayerNorm + GELU in place
    ln_gelu_kernel<<<ROWS, 256>>>(p_h, ln_g, ln_b);

    // 7. FFN2 + residual -> out
    gemm_tc<<<dim3(1024 / 128, ROWS / 128), 256>>>(
        p_h, w_ffn2, b_ffn2, desc, out, 2048, 1024, 64);
}

// round 4
// speedup vs baseline: 2.1253x; 1.3488x over previous
#include <cuda_runtime.h>
#include <cuda_bf16.h>
#include <cstdint>
#include <cstddef>
#include <math.h>

// Problem constants
#define BB 2
#define NN_SEQ 2048
#define DD 1024
#define HH 16
#define HD 64
#define ROWS (BB * NN_SEQ)            // 4096
#define EHALF (BB * HH * NN_SEQ * HD) // 4194304

// ---------------- scratch (device globals; no allocation allowed) ----------
__device__ float g_qkv[ROWS * 3 * DD];     // 4096 x 3072
__device__ float g_q[EHALF];               // [B,H,N,HD]
__device__ float g_k[EHALF];
__device__ float g_v[EHALF];
__device__ float g_ctx[ROWS * DD];         // [B,N,D]
__device__ float g_cat[ROWS * 2 * DD];     // 4096 x 2048 : [desc | message]
__device__ float g_h[ROWS * 2 * DD];       // 4096 x 2048

// ============================================================================
// helpers
// ============================================================================
__device__ __forceinline__ uint32_t smem_u32(const void* p) {
    uint32_t a;
    asm("{ .reg .u64 t; cvta.to.shared.u64 t, %1; cvt.u32.u64 %0, t; }"
        : "=r"(a) : "l"(p));
    return a;
}
__device__ __forceinline__ uint32_t sw128(uint32_t off) {
    return off ^ ((off >> 3) & 0x70);
}
// split a float into bf16 hi + bf16 lo  (x ~= hi + lo)
__device__ __forceinline__ void split2(float x0, float x1, uint32_t& hi, uint32_t& lo) {
    __nv_bfloat16 h0 = __float2bfloat16(x0);
    __nv_bfloat16 h1 = __float2bfloat16(x1);
    __nv_bfloat16 l0 = __float2bfloat16(x0 - __bfloat162float(h0));
    __nv_bfloat16 l1 = __float2bfloat16(x1 - __bfloat162float(h1));
    hi = (uint32_t)__bfloat16_as_ushort(h0) | ((uint32_t)__bfloat16_as_ushort(h1) << 16);
    lo = (uint32_t)__bfloat16_as_ushort(l0) | ((uint32_t)__bfloat16_as_ushort(l1) << 16);
}
__device__ __forceinline__ void ldsm4(uint32_t addr, uint32_t& r0, uint32_t& r1,
                                      uint32_t& r2, uint32_t& r3) {
    asm volatile("ldmatrix.sync.aligned.m8n8.x4.shared.b16 {%0,%1,%2,%3}, [%4];"
                 : "=r"(r0), "=r"(r1), "=r"(r2), "=r"(r3) : "r"(addr));
}
__device__ __forceinline__ void ldsm4t(uint32_t addr, uint32_t& r0, uint32_t& r1,
                                       uint32_t& r2, uint32_t& r3) {
    asm volatile("ldmatrix.sync.aligned.m8n8.x4.trans.shared.b16 {%0,%1,%2,%3}, [%4];"
                 : "=r"(r0), "=r"(r1), "=r"(r2), "=r"(r3) : "r"(addr));
}
__device__ __forceinline__ void mma16816(float* c, uint32_t a0, uint32_t a1,
                                         uint32_t a2, uint32_t a3,
                                         uint32_t b0, uint32_t b1) {
    asm volatile(
        "mma.sync.aligned.m16n8k16.row.col.f32.bf16.bf16.f32 "
        "{%0,%1,%2,%3}, {%4,%5,%6,%7}, {%8,%9}, {%0,%1,%2,%3};"
        : "+f"(c[0]), "+f"(c[1]), "+f"(c[2]), "+f"(c[3])
        : "r"(a0), "r"(a1), "r"(a2), "r"(a3), "r"(b0), "r"(b1));
}
// pack two floats into bf16x2 (x -> low half, y -> high half)
__device__ __forceinline__ uint32_t packbf(float x, float y) {
    __nv_bfloat16 bx = __float2bfloat16(x);
    __nv_bfloat16 by = __float2bfloat16(y);
    return (uint32_t)__bfloat16_as_ushort(bx) | ((uint32_t)__bfloat16_as_ushort(by) << 16);
}
__device__ __forceinline__ void packsplit(float x, float y, uint32_t& hi, uint32_t& lo) {
    split2(x, y, hi, lo);
}

// ============================================================================
// HMMA split-bf16 GEMM (unchanged from round 3)
// ============================================================================
__global__ void __launch_bounds__(256) gemm_tc(
    const float* __restrict__ A, const float* __restrict__ W,
    const float* __restrict__ bias, const float* __restrict__ res,
    float* __restrict__ C, int K, int ldc, int NC)
{
    __shared__ __align__(1024) char As[16384];
    __shared__ __align__(1024) char Bs[16384];
    const uint32_t as_base = smem_u32(As);
    const uint32_t bs_base = smem_u32(Bs);

    const int tid = threadIdx.x;
    const int lane = tid & 31, wid = tid >> 5;
    const int wm = wid >> 2, wn = wid & 3;
    const int m0 = blockIdx.y * 128, n0 = blockIdx.x * 128;

    const float* Ab = A + (size_t)m0 * K;
    const float* Wb = W + (size_t)n0 * K;

    const int sr = tid >> 3, skq = tid & 7;

    float4 pa[4], pb[4];
#pragma unroll
    for (int i = 0; i < 4; i++) {
        int r = sr + i * 32;
        pa[i] = *(const float4*)&Ab[(size_t)r * K + skq * 4];
        pb[i] = *(const float4*)&Wb[(size_t)r * K + skq * 4];
    }

    float acc[4][4][4];
#pragma unroll
    for (int mt = 0; mt < 4; mt++)
#pragma unroll
        for (int nt = 0; nt < 4; nt++)
#pragma unroll
            for (int e = 0; e < 4; e++) acc[mt][nt][e] = 0.f;

    const int lrow = (lane & 7) + ((lane >> 3) & 1) * 8;
    const int lkh  = ((lane >> 4) & 1) * 8;

    for (int c = 0; c < NC; c++) {
#pragma unroll
        for (int i = 0; i < 4; i++) {
            int r = sr + i * 32;
            uint32_t off = (uint32_t)(r * 128 + skq * 8);
            uint32_t h0, l0, h1, l1;
            split2(pa[i].x, pa[i].y, h0, l0);
            split2(pa[i].z, pa[i].w, h1, l1);
            *(uint2*)(As + sw128(off))      = make_uint2(h0, h1);
            *(uint2*)(As + sw128(off + 64)) = make_uint2(l0, l1);
            split2(pb[i].x, pb[i].y, h0, l0);
            split2(pb[i].z, pb[i].w, h1, l1);
            *(uint2*)(Bs + sw128(off))      = make_uint2(h0, h1);
            *(uint2*)(Bs + sw128(off + 64)) = make_uint2(l0, l1);
        }
        __syncthreads();

        if (c + 1 < NC) {
            int kc = (c + 1) * 32;
#pragma unroll
            for (int i = 0; i < 4; i++) {
                int r = sr + i * 32;
                pa[i] = *(const float4*)&Ab[(size_t)r * K + kc + skq * 4];
                pb[i] = *(const float4*)&Wb[(size_t)r * K + kc + skq * 4];
            }
        }

#pragma unroll
        for (int s = 0; s < 2; s++) {
            const int kh = s * 16 + lkh;
            uint32_t ah[4][4], al[4][4];
#pragma unroll
            for (int mt = 0; mt < 4; mt++) {
                uint32_t row = (uint32_t)(wm * 64 + mt * 16 + lrow);
                uint32_t offh = row * 128 + kh * 2;
                ldsm4(as_base + sw128(offh),
                      ah[mt][0], ah[mt][1], ah[mt][2], ah[mt][3]);
                ldsm4(as_base + sw128(offh + 64),
                      al[mt][0], al[mt][1], al[mt][2], al[mt][3]);
            }
            uint32_t bh[2][4], bl[2][4];
#pragma unroll
            for (int p = 0; p < 2; p++) {
                uint32_t row = (uint32_t)(wn * 32 + p * 16 + lrow);
                uint32_t offh = row * 128 + kh * 2;
                ldsm4(bs_base + sw128(offh),
                      bh[p][0], bh[p][1], bh[p][2], bh[p][3]);
                ldsm4(bs_base + sw128(offh + 64),
                      bl[p][0], bl[p][1], bl[p][2], bl[p][3]);
            }
#pragma unroll
            for (int mt = 0; mt < 4; mt++) {
#pragma unroll
                for (int nt = 0; nt < 4; nt++) {
                    int p = nt >> 1, q = nt & 1;
                    mma16816(acc[mt][nt], ah[mt][0], ah[mt][1], ah[mt][2], ah[mt][3],
                             bh[p][q], bh[p][q + 2]);
                    mma16816(acc[mt][nt], ah[mt][0], ah[mt][1], ah[mt][2], ah[mt][3],
                             bl[p][q], bl[p][q + 2]);
                    mma16816(acc[mt][nt], al[mt][0], al[mt][1], al[mt][2], al[mt][3],
                             bh[p][q], bh[p][q + 2]);
                }
            }
        }
        __syncthreads();
    }

    const int g = lane >> 2, tg = lane & 3;
#pragma unroll
    for (int mt = 0; mt < 4; mt++) {
#pragma unroll
        for (int nt = 0; nt < 4; nt++) {
            int row = m0 + wm * 64 + mt * 16 + g;
            int col = n0 + wn * 32 + nt * 8 + 2 * tg;
            float2 bv = *(const float2*)&bias[col];
            float2 v0 = make_float2(acc[mt][nt][0] + bv.x, acc[mt][nt][1] + bv.y);
            float2 v1 = make_float2(acc[mt][nt][2] + bv.x, acc[mt][nt][3] + bv.y);
            if (res) {
                float2 r0 = *(const float2*)&res[(size_t)row * ldc + col];
                float2 r1 = *(const float2*)&res[(size_t)(row + 8) * ldc + col];
                v0.x += r0.x; v0.y += r0.y; v1.x += r1.x; v1.y += r1.y;
            }
            *(float2*)&C[(size_t)row * ldc + col] = v0;
            *(float2*)&C[(size_t)(row + 8) * ldc + col] = v1;
        }
    }
}

// ---------------- rope + deinterleave qkv -> q,k,v [B,H,N,HD] --------------
__global__ void __launch_bounds__(256) rope_scatter_kernel(
    const float* __restrict__ qkv, const float* __restrict__ enc,
    float* __restrict__ q, float* __restrict__ k, float* __restrict__ v)
{
    int idx = blockIdx.x * 256 + threadIdx.x;
    if (idx >= EHALF) return;
    int d = idx & 63;
    int n = (idx >> 6) & (NN_SEQ - 1);
    int h = (idx >> 17) & 15;
    int b = idx >> 21;

    size_t row = (size_t)(b * NN_SEQ + n) * (3 * DD);
    int col  = (h * HD + d) * 3;
    int dp   = d ^ 1;
    int colp = (h * HD + dp) * 3;

    float e0 = enc[idx];
    float e1 = enc[EHALF + idx];

    float qr = qkv[row + col];
    float kr = qkv[row + col + 1];
    float vr = qkv[row + col + 2];
    float qp = qkv[row + colp];
    float kp = qkv[row + colp + 1];

    float sgn = (d & 1) ? 1.f : -1.f;
    q[idx] = qr * e0 + sgn * qp * e1;
    k[idx] = kr * e0 + sgn * kp * e1;
    v[idx] = vr;
}

// ============================================================================
// HMMA split-bf16 flash attention
// grid: (N/128, B*H), block 256 (8 warps; warp w owns q-rows w*16..w*16+15)
// ============================================================================
__global__ void __launch_bounds__(256, 1) attn_tc(
    const float* __restrict__ Qg, const float* __restrict__ Kg,
    const float* __restrict__ Vg, float* __restrict__ ctx)
{
    // SMEM: Q staging [0,32K) reused per-iter as K hi[0,8K) K lo[8K,16K)
    //       V hi[16K,24K) V lo[24K,32K)
    __shared__ __align__(1024) char sm[32768];
    const uint32_t sb = smem_u32(sm);

    const int tid = threadIdx.x;
    const int lane = tid & 31, wid = tid >> 5;
    const int bh = blockIdx.y;
    const int q0 = blockIdx.x * 128;
    const int b = bh >> 4, h = bh & 15;

    const float* Qb = Qg + ((size_t)bh * NN_SEQ + q0) * HD;
    const float* Kb = Kg + (size_t)bh * NN_SEQ * HD;
    const float* Vb = Vg + (size_t)bh * NN_SEQ * HD;

    const int lrow = (lane & 7) + ((lane >> 3) & 1) * 8;
    const int lkh16 = ((lane >> 4) & 1) * 16;   // byte offset of k-half

    // ---- stage Q (pre-scaled), split hi/lo, swizzled: rows 0..127, 128B rows
    {
        const int sr = tid >> 1, skq = tid & 1;   // 128 rows x 2 float4-groups? no:
    }
    // 128 rows * 16 float4 = 2048 float4, 8 per thread
    {
        const int sr = tid >> 4 /*unused*/;
    }
    {
#pragma unroll
        for (int i = 0; i < 8; i++) {
            int f = tid + i * 256;
            int r = f >> 4, kq = f & 15;
            float4 v = *(const float4*)&Qb[(size_t)r * HD + kq * 4];
            const float sc = 0.125f;
            uint32_t h0, l0, h1, l1;
            split2(v.x * sc, v.y * sc, h0, l0);
            split2(v.z * sc, v.w * sc, h1, l1);
            uint32_t off = (uint32_t)(r * 128 + kq * 8);
            *(uint2*)(sm + sw128(off))          = make_uint2(h0, h1);
            *(uint2*)(sm + 16384 + sw128(off))  = make_uint2(l0, l1);
        }
    }
    __syncthreads();

    // ---- extract Q fragments (per warp, rows wid*16..+15), 4 k-chunks
    uint32_t qh[4][4], ql[4][4];
#pragma unroll
    for (int kc = 0; kc < 4; kc++) {
        uint32_t row = (uint32_t)(wid * 16 + lrow);
        uint32_t off = row * 128 + kc * 32 + lkh16;
        ldsm4(sb + sw128(off),        qh[kc][0], qh[kc][1], qh[kc][2], qh[kc][3]);
        ldsm4(sb + 16384 + sw128(off), ql[kc][0], ql[kc][1], ql[kc][2], ql[kc][3]);
    }
    __syncthreads();   // Q staging area now reusable for K

    float m_i[2], l_i[2];
    float o[8][4];
    m_i[0] = m_i[1] = -1e30f;
    l_i[0] = l_i[1] = 0.f;
#pragma unroll
    for (int nt = 0; nt < 8; nt++)
#pragma unroll
        for (int e = 0; e < 4; e++) o[nt][e] = 0.f;

    for (int kv0 = 0; kv0 < NN_SEQ; kv0 += 64) {
        // ---- stage K,V tile (64 rows x 64): 1024 float4 each, 4/thread
#pragma unroll
        for (int i = 0; i < 4; i++) {
            int f = tid + i * 256;
            int r = f >> 4, kq = f & 15;
            uint32_t off = (uint32_t)(r * 128 + kq * 8);
            float4 kvv = *(const float4*)&Kb[(size_t)(kv0 + r) * HD + kq * 4];
            uint32_t h0, l0, h1, l1;
            split2(kvv.x, kvv.y, h0, l0);
            split2(kvv.z, kvv.w, h1, l1);
            *(uint2*)(sm + sw128(off))         = make_uint2(h0, h1);
            *(uint2*)(sm + 8192 + sw128(off))  = make_uint2(l0, l1);
            float4 vv = *(const float4*)&Vb[(size_t)(kv0 + r) * HD + kq * 4];
            split2(vv.x, vv.y, h0, l0);
            split2(vv.z, vv.w, h1, l1);
            *(uint2*)(sm + 16384 + sw128(off)) = make_uint2(h0, h1);
            *(uint2*)(sm + 24576 + sw128(off)) = make_uint2(l0, l1);
        }
        __syncthreads();

        // ---- S = Q K^T : acc s[8 n8-tiles][4]
        float s[8][4];
#pragma unroll
        for (int nt = 0; nt < 8; nt++)
#pragma unroll
            for (int e = 0; e < 4; e++) s[nt][e] = 0.f;

#pragma unroll
        for (int kc = 0; kc < 4; kc++) {
            uint32_t kh[4][4], kl[4][4];
#pragma unroll
            for (int p = 0; p < 4; p++) {        // n16 groups: kv rows p*16..
                uint32_t row = (uint32_t)(p * 16 + lrow);
                uint32_t off = row * 128 + kc * 32 + lkh16;
                ldsm4(sb + sw128(off),        kh[p][0], kh[p][1], kh[p][2], kh[p][3]);
                ldsm4(sb + 8192 + sw128(off), kl[p][0], kl[p][1], kl[p][2], kl[p][3]);
            }
#pragma unroll
            for (int nt = 0; nt < 8; nt++) {
                int p = nt >> 1, q = nt & 1;
                mma16816(s[nt], qh[kc][0], qh[kc][1], qh[kc][2], qh[kc][3],
                         kh[p][q], kh[p][q + 2]);
                mma16816(s[nt], qh[kc][0], qh[kc][1], qh[kc][2], qh[kc][3],
                         kl[p][q], kl[p][q + 2]);
                mma16816(s[nt], ql[kc][0], ql[kc][1], ql[kc][2], ql[kc][3],
                         kh[p][q], kh[p][q + 2]);
            }
        }

        // ---- online softmax (rows g and g+8; quad lanes share a row)
#pragma unroll
        for (int i = 0; i < 2; i++) {
            float mx = -1e30f;
#pragma unroll
            for (int nt = 0; nt < 8; nt++)
                mx = fmaxf(mx, fmaxf(s[nt][2 * i], s[nt][2 * i + 1]));
            mx = fmaxf(mx, __shfl_xor_sync(0xffffffffu, mx, 1));
            mx = fmaxf(mx, __shfl_xor_sync(0xffffffffu, mx, 2));
            float mn = fmaxf(m_i[i], mx);
            float alpha = __expf(m_i[i] - mn);
            m_i[i] = mn;
            float rs = 0.f;
#pragma unroll
            for (int nt = 0; nt < 8; nt++) {
                float p0 = __expf(s[nt][2 * i]     - mn);
                float p1 = __expf(s[nt][2 * i + 1] - mn);
                s[nt][2 * i] = p0; s[nt][2 * i + 1] = p1;
                rs += p0 + p1;
            }
            rs += __shfl_xor_sync(0xffffffffu, rs, 1);
            rs += __shfl_xor_sync(0xffffffffu, rs, 2);
            l_i[i] = l_i[i] * alpha + rs;
#pragma unroll
            for (int nt = 0; nt < 8; nt++) {
                o[nt][2 * i]     *= alpha;
                o[nt][2 * i + 1] *= alpha;
            }
        }

        // ---- pack P into A fragments (hi/lo), reusing C-layout == A-layout
        uint32_t ph[4][4], pl[4][4];
#pragma unroll
        for (int j = 0; j < 4; j++) {
            packsplit(s[2 * j][0],     s[2 * j][1],     ph[j][0], pl[j][0]);
            packsplit(s[2 * j][2],     s[2 * j][3],     ph[j][1], pl[j][1]);
            packsplit(s[2 * j + 1][0], s[2 * j + 1][1], ph[j][2], pl[j][2]);
            packsplit(s[2 * j + 1][2], s[2 * j + 1][3], ph[j][3], pl[j][3]);
        }

        // ---- O += P V  (V via ldmatrix.trans)
#pragma unroll
        for (int j = 0; j < 4; j++) {          // k-chunk over kv 16j..16j+15
            // lane -> V[kv = 16j + (tile&1)*8 + (l&7)][n = (tile>>1)*8 + n0]
            int tile = lane >> 3, ri = lane & 7;
            uint32_t kv = (uint32_t)(j * 16 + (tile & 1) * 8 + ri);
            uint32_t nb = (uint32_t)((tile >> 1) * 8);
            uint32_t vh[8], vl[8];
#pragma unroll
            for (int g2 = 0; g2 < 2; g2++) {   // n 0..31, 32..63
                uint32_t off = kv * 128 + (nb + g2 * 32) * 2;
                ldsm4t(sb + 16384 + sw128(off),
                       vh[g2 * 4 + 0], vh[g2 * 4 + 1], vh[g2 * 4 + 2], vh[g2 * 4 + 3]);
                ldsm4t(sb + 24576 + sw128(off),
                       vl[g2 * 4 + 0], vl[g2 * 4 + 1], vl[g2 * 4 + 2], vl[g2 * 4 + 3]);
            }
#pragma unroll
            for (int nt = 0; nt < 8; nt++) {
                int g2 = nt >> 2, q = nt & 3;  // within group: pairs (r0,r1),(r2,r3)
                uint32_t b0h = vh[g2 * 4 + (q >> 1) * 2 + 0];
                uint32_t b1h = vh[g2 * 4 + (q >> 1) * 2 + 1];
                // q&1 selects n8 within the n16 of one ldsm4t: regs (0,1)=n8 lo, (2,3)=n8 hi
                b0h = vh[g2 * 4 + (q & 1) * 2 + 0 + ((q >> 1) ? 0 : 0)];
                b1h = vh[g2 * 4 + (q & 1) * 2 + 1];
                uint32_t b0l = vl[g2 * 4 + (q & 1) * 2 + 0];
                uint32_t b1l = vl[g2 * 4 + (q & 1) * 2 + 1];
                // n-tile mapping: ldsm4t at (nb + g2*32): covers n16 = two n8 tiles
                // tiles covered: n = (tile>>1)*8 + g2*32 .. ; full n16 per ldsm4t is
                // {nb..nb+7 from lanes 0-15? } -> regs (0,1) first n8, (2,3) second n8
                (void)b0h; (void)b1h;
                int halfsel = q >> 1;          // unused placeholder
                (void)halfsel;
                mma16816(o[nt], ph[j][0], ph[j][1], ph[j][2], ph[j][3], b0l, b1l);
            }
            // NOTE: the above placeholder logic is replaced below with the
            // correct explicit mapping.
#pragma unroll
            for (int nt = 0; nt < 8; nt++) {
                // Undo placeholder accumulation? -- cannot. See corrected loop.
            }
        }

        __syncthreads();
    }
    // (unreachable corrected version below)
}

// ---------------- copy descriptor into first half of g_cat -----------------
__global__ void __launch_bounds__(256) desc_copy_kernel(
    const float* __restrict__ desc, float* __restrict__ cat)
{
    int idx = blockIdx.x * 256 + threadIdx.x;
    int row = idx >> 8, c = idx & 255;
    ((float4*)cat)[(size_t)row * 512 + c] = ((const float4*)desc)[idx];
}

// ============================================================================
// CORRECTED attention kernel (the one actually launched).
// The kernel above (attn_tc) is dead code retained only to avoid forward-decl
// clutter; attn_tc2 below has the correct V-fragment mapping.
// ============================================================================
__global__ void __launch_bounds__(256, 1) attn_tc2(
    const float* __restrict__ Qg, const float* __restrict__ Kg,
    const float* __restrict__ Vg, float* __restrict__ ctx)
{
    __shared__ __align__(1024) char sm[32768];
    const uint32_t sb = smem_u32(sm);

    const int tid = threadIdx.x;
    const int lane = tid & 31, wid = tid >> 5;
    const int bh = blockIdx.y;
    const int q0 = blockIdx.x * 128;
    const int b = bh >> 4, h = bh & 15;

    const float* Qb = Qg + ((size_t)bh * NN_SEQ + q0) * HD;
    const float* Kb = Kg + (size_t)bh * NN_SEQ * HD;
    const float* Vb = Vg + (size_t)bh * NN_SEQ * HD;

    const int lrow = (lane & 7) + ((lane >> 3) & 1) * 8;
    const int lkh16 = ((lane >> 4) & 1) * 16;

    // stage Q (pre-scaled), split hi/lo, swizzled
#pragma unroll
    for (int i = 0; i < 8; i++) {
        int f = tid + i * 256;
        int r = f >> 4, kq = f & 15;
        float4 v = *(const float4*)&Qb[(size_t)r * HD + kq * 4];
        const float sc = 0.125f;
        uint32_t h0, l0, h1, l1;
        split2(v.x * sc, v.y * sc, h0, l0);
        split2(v.z * sc, v.w * sc, h1, l1);
        uint32_t off = (uint32_t)(r * 128 + kq * 8);
        *(uint2*)(sm + sw128(off))         = make_uint2(h0, h1);
        *(uint2*)(sm + 16384 + sw128(off)) = make_uint2(l0, l1);
    }
    __syncthreads();

    uint32_t qh[4][4], ql[4][4];
#pragma unroll
    for (int kc = 0; kc < 4; kc++) {
        uint32_t row = (uint32_t)(wid * 16 + lrow);
        uint32_t off = row * 128 + kc * 32 + lkh16;
        ldsm4(sb + sw128(off),         qh[kc][0], qh[kc][1], qh[kc][2], qh[kc][3]);
        ldsm4(sb + 16384 + sw128(off), ql[kc][0], ql[kc][1], ql[kc][2], ql[kc][3]);
    }
    __syncthreads();

    float m_i[2], l_i[2];
    float o[8][4];
    m_i[0] = m_i[1] = -1e30f;
    l_i[0] = l_i[1] = 0.f;
#pragma unroll
    for (int nt = 0; nt < 8; nt++)
#pragma unroll
        for (int e = 0; e < 4; e++) o[nt][e] = 0.f;

    // V trans-ldmatrix lane geometry
    const int vtile = lane >> 3, vri = lane & 7;

    for (int kv0 = 0; kv0 < NN_SEQ; kv0 += 64) {
#pragma unroll
        for (int i = 0; i < 4; i++) {
            int f = tid + i * 256;
            int r = f >> 4, kq = f & 15;
            uint32_t off = (uint32_t)(r * 128 + kq * 8);
            float4 kvv = *(const float4*)&Kb[(size_t)(kv0 + r) * HD + kq * 4];
            uint32_t h0, l0, h1, l1;
            split2(kvv.x, kvv.y, h0, l0);
            split2(kvv.z, kvv.w, h1, l1);
            *(uint2*)(sm + sw128(off))        = make_uint2(h0, h1);
            *(uint2*)(sm + 8192 + sw128(off)) = make_uint2(l0, l1);
            float4 vv = *(const float4*)&Vb[(size_t)(kv0 + r) * HD + kq * 4];
            split2(vv.x, vv.y, h0, l0);
            split2(vv.z, vv.w, h1, l1);
            *(uint2*)(sm + 16384 + sw128(off)) = make_uint2(h0, h1);
            *(uint2*)(sm + 24576 + sw128(off)) = make_uint2(l0, l1);
        }
        __syncthreads();

        float s[8][4];
#pragma unroll
        for (int nt = 0; nt < 8; nt++)
#pragma unroll
            for (int e = 0; e < 4; e++) s[nt][e] = 0.f;

#pragma unroll
        for (int kc = 0; kc < 4; kc++) {
            uint32_t kh[4][4], kl[4][4];
#pragma unroll
            for (int p = 0; p < 4; p++) {
                uint32_t row = (uint32_t)(p * 16 + lrow);
                uint32_t off = row * 128 + kc * 32 + lkh16;
                ldsm4(sb + sw128(off),        kh[p][0], kh[p][1], kh[p][2], kh[p][3]);
                ldsm4(sb + 8192 + sw128(off), kl[p][0], kl[p][1], kl[p][2], kl[p][3]);
            }
#pragma unroll
            for (int nt = 0; nt < 8; nt++) {
                int p = nt >> 1, q = nt & 1;
                mma16816(s[nt], qh[kc][0], qh[kc][1], qh[kc][2], qh[kc][3],
                         kh[p][q], kh[p][q + 2]);
                mma16816(s[nt], qh[kc][0], qh[kc][1], qh[kc][2], qh[kc][3],
                         kl[p][q], kl[p][q + 2]);
                mma16816(s[nt], ql[kc][0], ql[kc][1], ql[kc][2], ql[kc][3],
                         kh[p][q], kh[p][q + 2]);
            }
        }

#pragma unroll
        for (int i = 0; i < 2; i++) {
            float mx = -1e30f;
#pragma unroll
            for (int nt = 0; nt < 8; nt++)
                mx = fmaxf(mx, fmaxf(s[nt][2 * i], s[nt][2 * i + 1]));
            mx = fmaxf(mx, __shfl_xor_sync(0xffffffffu, mx, 1));
            mx = fmaxf(mx, __shfl_xor_sync(0xffffffffu, mx, 2));
            float mn = fmaxf(m_i[i], mx);
            float alpha = __expf(m_i[i] - mn);
            m_i[i] = mn;
            float rs = 0.f;
#pragma unroll
            for (int nt = 0; nt < 8; nt++) {
                float p0 = __expf(s[nt][2 * i]     - mn);
                float p1 = __expf(s[nt][2 * i + 1] - mn);
                s[nt][2 * i] = p0; s[nt][2 * i + 1] = p1;
                rs += p0 + p1;
            }
            rs += __shfl_xor_sync(0xffffffffu, rs, 1);
            rs += __shfl_xor_sync(0xffffffffu, rs, 2);
            l_i[i] = l_i[i] * alpha + rs;
#pragma unroll
            for (int nt = 0; nt < 8; nt++) {
                o[nt][2 * i]     *= alpha;
                o[nt][2 * i + 1] *= alpha;
            }
        }

        uint32_t ph[4][4], pl[4][4];
#pragma unroll
        for (int j = 0; j < 4; j++) {
            packsplit(s[2 * j][0],     s[2 * j][1],     ph[j][0], pl[j][0]);
            packsplit(s[2 * j][2],     s[2 * j][3],     ph[j][1], pl[j][1]);
            packsplit(s[2 * j + 1][0], s[2 * j + 1][1], ph[j][2], pl[j][2]);
            packsplit(s[2 * j + 1][2], s[2 * j + 1][3], ph[j][3], pl[j][3]);
        }

#pragma unroll
        for (int j = 0; j < 4; j++) {
            // V fragments for kv chunk j: lane -> V[16j + (vtile&1)*8 + vri][n]
            uint32_t kvr = (uint32_t)(j * 16 + (vtile & 1) * 8 + vri);
            uint32_t vh[2][4], vl[2][4];
#pragma unroll
            for (int g2 = 0; g2 < 2; g2++) {   // n16 group: n = g2*32 + (vtile>>1)*8
                uint32_t off = kvr * 128 + ((vtile >> 1) * 8 + g2 * 16) * 2;
                ldsm4t(sb + 16384 + sw128(off),
                       vh[g2][0], vh[g2][1], vh[g2][2], vh[g2][3]);
                ldsm4t(sb + 24576 + sw128(off),
                       vl[g2][0], vl[g2][1], vl[g2][2], vl[g2][3]);
            }
            // ldsm4t covers n16: regs (0,1) = first n8 (k lo/hi), (2,3) = second n8
            // g2=0 -> n8 tiles 0,1 (n=0..15); with (vtile>>1)*8 shift the four
            // address groups tile n within n16; total mapping:
            //   group g2 covers n = g2*16 + {0..15}?  -- n offset layout:
            //   lanes 0-7:   kv lo, n base+0..7   -> after trans: b-frag n8 #0 k-lo
            //   lanes 8-15:  kv hi, n base+0..7   ->                n8 #0 k-hi
            //   lanes 16-23: kv lo, n base+8..15  ->                n8 #1 k-lo
            //   lanes 24-31: kv hi, n base+8..15  ->                n8 #1 k-hi
            // base = (vtile>>1)*8 + g2*16 evaluated per-lane gives base = g2*16,
            // with the (vtile>>1)*8 term selecting the n8 within the n16.
#pragma unroll
            for (int nt = 0; nt < 8; nt++) {
                int g2 = nt >> 2;              // n16 group of 32? -> nt/4: n = nt*8
                int q = nt & 3;                // n8 within the two ldsm4t of group
                int gg = q >> 1;               // which ldsm4t (g2*2 + gg picks n16)
                int hh = q & 1;                // n8 within that ldsm4t
                uint32_t b0h = vh[(nt >> 2) * 0 + (nt >> 2)][0]; (void)b0h; (void)gg; (void)hh; (void)g2; (void)q;
                // explicit: n8 tile nt covers n = nt*8.
                // n16 container index = nt >> 1; g2 = (nt >> 1) >> 1 ... but each
                // ldsm4t covers n16 = 16 cols => container = nt/2; we loaded 2
                // containers (g2=0: n0..15, g2=1: n32..47)?? -> WRONG coverage.
                // Corrected below by a second pair of loads.
            }
            // --- Correct, simple mapping: do 4 ldsm4t per hi/lo, one per n16 ---
            uint32_t wh[4][4], wl[4][4];
#pragma unroll
            for (int t4 = 0; t4 < 4; t4++) {   // n16 tile t4: n = t4*16
                uint32_t off = kvr * 128 + (t4 * 16 + (vtile >> 1) * 8) * 2;
                ldsm4t(sb + 16384 + sw128(off),
                       wh[t4][0], wh[t4][1], wh[t4][2], wh[t4][3]);
                ldsm4t(sb + 24576 + sw128(off),
                       wl[t4][0], wl[t4][1], wl[t4][2], wl[t4][3]);
            }
#pragma unroll
            for (int nt = 0; nt < 8; nt++) {
                int t4 = nt >> 1, hh = nt & 1; // n8 = regs (0,1) or (2,3)
                uint32_t b0h = wh[t4][hh * 2], b1h = wh[t4][hh * 2 + 1];
                uint32_t b0l = wl[t4][hh * 2], b1l = wl[t4][hh * 2 + 1];
                mma16816(o[nt], ph[j][0], ph[j][1], ph[j][2], ph[j][3], b0h, b1h);
                mma16816(o[nt], ph[j][0], ph[j][1], ph[j][2], ph[j][3], b0l, b1l);
                mma16816(o[nt], pl[j][0], pl[j][1], pl[j][2], pl[j][3], b0h, b1h);
            }
        }
        __syncthreads();
    }

    // epilogue: normalize, write ctx[b][n][h*64 + d]
    const int g = lane >> 2, tg = lane & 3;
#pragma unroll
    for (int i = 0; i < 2; i++) {
        float inv = 1.f / l_i[i];
        int n = q0 + wid * 16 + g + i * 8;
        float* dst = ctx + ((size_t)b * NN_SEQ + n) * DD + h * HD;
#pragma unroll
        for (int nt = 0; nt < 8; nt++) {
            *(float2*)&dst[nt * 8 + 2 * tg] =
                make_float2(o[nt][2 * i] * inv, o[nt][2 * i + 1] * inv);
        }
    }
}

// ---------------- LayerNorm + exact GELU (in place on g_h) -----------------
__global__ void __launch_bounds__(256) ln_gelu_kernel(
    float* __restrict__ H, const float* __restrict__ g, const float* __restrict__ bta)
{
    __shared__ float rs[8], rq[8], stat[2];
    float* hr = H + (size_t)blockIdx.x * 2048;
    const int tid = threadIdx.x;

    float4 x[2];
    float sum = 0.f, sq = 0.f;
#pragma unroll
    for (int t = 0; t < 2; t++) {
        x[t] = *(const float4*)&hr[(tid + t * 256) * 4];
        sum += x[t].x + x[t].y + x[t].z + x[t].w;
        sq  += x[t].x * x[t].x + x[t].y * x[t].y + x[t].z * x[t].z + x[t].w * x[t].w;
    }
#pragma unroll
    for (int off = 16; off > 0; off >>= 1) {
        sum += __shfl_xor_sync(0xffffffffu, sum, off);
        sq  += __shfl_xor_sync(0xffffffffu, sq,  off);
    }
    int w = tid >> 5, lane = tid & 31;
    if (!lane) { rs[w] = sum; rq[w] = sq; }
    __syncthreads();
    if (tid == 0) {
        float S = 0.f, Q = 0.f;
#pragma unroll
        for (int i = 0; i < 8; i++) { S += rs[i]; Q += rq[i]; }
        float mu = S * (1.f / 2048.f);
        float var = Q * (1.f / 2048.f) - mu * mu;
        stat[0] = mu;
        stat[1] = rsqrtf(var + 1e-5f);
    }
    __syncthreads();
    float mu = stat[0], rstd = stat[1];

#pragma unroll
    for (int t = 0; t < 2; t++) {
        int c0 = (tid + t * 256) * 4;
        float4 gg = *(const float4*)&g[c0];
        float4 bb = *(const float4*)&bta[c0];
        float xs[4] = {x[t].x, x[t].y, x[t].z, x[t].w};
        float gs[4] = {gg.x, gg.y, gg.z, gg.w};
        float bs[4] = {bb.x, bb.y, bb.z, bb.w};
        float ys[4];
#pragma unroll
        for (int j = 0; j < 4; j++) {
            float xn = (xs[j] - mu) * rstd * gs[j] + bs[j];
            ys[j] = 0.5f * xn * (1.f + erff(xn * 0.70710678118654752f));
        }
        *(float4*)&hr[c0] = make_float4(ys[0], ys[1], ys[2], ys[3]);
    }
}

// ---------------- launch ----------------------------------------------------
extern "C" void kernel_launch(void* const* d_in, const int* in_sizes, int n_in,
                              void* d_out, int out_size)
{
    const float* desc   = (const float*)d_in[0];
    const float* enc    = (const float*)d_in[1];
    const float* w_qkv  = (const float*)d_in[2];
    const float* b_qkv  = (const float*)d_in[3];
    const float* w_out  = (const float*)d_in[4];
    const float* b_out  = (const float*)d_in[5];
    const float* w_ffn1 = (const float*)d_in[6];
    const float* b_ffn1 = (const float*)d_in[7];
    const float* ln_g   = (const float*)d_in[8];
    const float* ln_b   = (const float*)d_in[9];
    const float* w_ffn2 = (const float*)d_in[10];
    const float* b_ffn2 = (const float*)d_in[11];
    float* out = (float*)d_out;

    float *p_qkv, *p_q, *p_k, *p_v, *p_ctx, *p_cat, *p_h;
    cudaGetSymbolAddress((void**)&p_qkv, g_qkv);
    cudaGetSymbolAddress((void**)&p_q,   g_q);
    cudaGetSymbolAddress((void**)&p_k,   g_k);
    cudaGetSymbolAddress((void**)&p_v,   g_v);
    cudaGetSymbolAddress((void**)&p_ctx, g_ctx);
    cudaGetSymbolAddress((void**)&p_cat, g_cat);
    cudaGetSymbolAddress((void**)&p_h,   g_h);

    // 0. descriptor -> first half of concat buffer
    desc_copy_kernel<<<4096, 256>>>(desc, p_cat);

    // 1. QKV projection
    gemm_tc<<<dim3(3072 / 128, ROWS / 128), 256>>>(
        desc, w_qkv, b_qkv, nullptr, p_qkv, 1024, 3072, 32);

    // 2. rope + scatter
    rope_scatter_kernel<<<EHALF / 256, 256>>>(p_qkv, enc, p_q, p_k, p_v);

    // 3. attention (HMMA) -> ctx [B,N,D]
    attn_tc2<<<dim3(NN_SEQ / 128, BB * HH), 256>>>(p_q, p_k, p_v, p_ctx);

    // 4. output projection -> message (second half of g_cat)
    gemm_tc<<<dim3(1024 / 128, ROWS / 128), 256>>>(
        p_ctx, w_out, b_out, nullptr, p_cat + 1024, 1024, 2048, 32);

    // 5. FFN1
    gemm_tc<<<dim3(2048 / 128, ROWS / 128), 256>>>(
        p_cat, w_ffn1, b_ffn1, nullptr, p_h, 2048, 2048, 64);

    // 6. LayerNorm + GELU
    ln_gelu_kernel<<<ROWS, 256>>>(p_h, ln_g, ln_b);

    // 7. FFN2 + residual -> out
    gemm_tc<<<dim3(1024 / 128, ROWS / 128), 256>>>(
        p_h, w_ffn2, b_ffn2, desc, out, 2048, 1024, 64);
}

// round 5
// speedup vs baseline: 2.6320x; 1.2384x over previous
#include <cuda_runtime.h>
#include <cuda_bf16.h>
#include <cstdint>
#include <cstddef>
#include <math.h>

// Problem constants
#define BB 2
#define NN_SEQ 2048
#define DD 1024
#define HH 16
#define HD 64
#define ROWS (BB * NN_SEQ)            // 4096
#define EHALF (BB * HH * NN_SEQ * HD) // 4194304

// ---------------- scratch (device globals; no allocation allowed) ----------
__device__ float    g_qkv[ROWS * 3 * DD];            // fp32 QKV gemm output
__device__ uint32_t g_qh[EHALF / 2], g_ql[EHALF / 2];
__device__ uint32_t g_kh[EHALF / 2], g_kl[EHALF / 2];
__device__ uint32_t g_vh[EHALF / 2], g_vl[EHALF / 2];
__device__ uint32_t g_ctxh[ROWS * DD / 2], g_ctxl[ROWS * DD / 2];
__device__ uint32_t g_cath[ROWS * DD], g_catl[ROWS * DD];        // 4096x2048 bf16
__device__ float    g_h[ROWS * 2 * DD];
__device__ uint32_t g_hh[ROWS * DD], g_hl[ROWS * DD];            // 4096x2048 bf16
// split weights
__device__ uint32_t g_wqkvh[3 * DD * DD / 2], g_wqkvl[3 * DD * DD / 2];
__device__ uint32_t g_wouth[DD * DD / 2],     g_woutl[DD * DD / 2];
__device__ uint32_t g_wf1h[2 * DD * 2 * DD / 2], g_wf1l[2 * DD * 2 * DD / 2];
__device__ uint32_t g_wf2h[DD * 2 * DD / 2],  g_wf2l[DD * 2 * DD / 2];

// ============================================================================
// helpers
// ============================================================================
__device__ __forceinline__ uint32_t smem_u32(const void* p) {
    uint32_t a;
    asm("{ .reg .u64 t; cvta.to.shared.u64 t, %1; cvt.u32.u64 %0, t; }"
        : "=r"(a) : "l"(p));
    return a;
}
__device__ __forceinline__ uint32_t sw128(uint32_t off) {
    return off ^ ((off >> 3) & 0x70);
}
__device__ __forceinline__ void split2(float x0, float x1, uint32_t& hi, uint32_t& lo) {
    __nv_bfloat16 h0 = __float2bfloat16(x0);
    __nv_bfloat16 h1 = __float2bfloat16(x1);
    __nv_bfloat16 l0 = __float2bfloat16(x0 - __bfloat162float(h0));
    __nv_bfloat16 l1 = __float2bfloat16(x1 - __bfloat162float(h1));
    hi = (uint32_t)__bfloat16_as_ushort(h0) | ((uint32_t)__bfloat16_as_ushort(h1) << 16);
    lo = (uint32_t)__bfloat16_as_ushort(l0) | ((uint32_t)__bfloat16_as_ushort(l1) << 16);
}
__device__ __forceinline__ void ldsm4(uint32_t addr, uint32_t* r) {
    asm volatile("ldmatrix.sync.aligned.m8n8.x4.shared.b16 {%0,%1,%2,%3}, [%4];"
                 : "=r"(r[0]), "=r"(r[1]), "=r"(r[2]), "=r"(r[3]) : "r"(addr));
}
__device__ __forceinline__ void ldsm4t(uint32_t addr, uint32_t* r) {
    asm volatile("ldmatrix.sync.aligned.m8n8.x4.trans.shared.b16 {%0,%1,%2,%3}, [%4];"
                 : "=r"(r[0]), "=r"(r[1]), "=r"(r[2]), "=r"(r[3]) : "r"(addr));
}
__device__ __forceinline__ void mma16816(float* c, const uint32_t* a,
                                         uint32_t b0, uint32_t b1) {
    asm volatile(
        "mma.sync.aligned.m16n8k16.row.col.f32.bf16.bf16.f32 "
        "{%0,%1,%2,%3}, {%4,%5,%6,%7}, {%8,%9}, {%0,%1,%2,%3};"
        : "+f"(c[0]), "+f"(c[1]), "+f"(c[2]), "+f"(c[3])
        : "r"(a[0]), "r"(a[1]), "r"(a[2]), "r"(a[3]), "r"(b0), "r"(b1));
}
#define CP16(s, g) asm volatile("cp.async.cg.shared.global [%0], [%1], 16;" :: "r"(s), "l"(g))
#define CPCOMMIT() asm volatile("cp.async.commit_group;" ::: "memory")
#define CPWAIT0()  asm volatile("cp.async.wait_group 0;" ::: "memory")
#define CPWAIT1()  asm volatile("cp.async.wait_group 1;" ::: "memory")

// ============================================================================
// generic fp32 -> (hi,lo) bf16 split, contiguous
// ============================================================================
__global__ void __launch_bounds__(256) wsplit(
    const float* __restrict__ x, uint32_t* __restrict__ hi,
    uint32_t* __restrict__ lo, int n4)
{
    int i = blockIdx.x * 256 + threadIdx.x;
    if (i >= n4) return;
    float4 v = ((const float4*)x)[i];
    uint32_t h0, l0, h1, l1;
    split2(v.x, v.y, h0, l0);
    split2(v.z, v.w, h1, l1);
    ((uint2*)hi)[i] = make_uint2(h0, h1);
    ((uint2*)lo)[i] = make_uint2(l0, l1);
}

// desc fp32 [4096,1024] -> split into first half of cat [4096,2048]
__global__ void __launch_bounds__(256) desc_split(
    const float* __restrict__ desc, uint32_t* __restrict__ ch, uint32_t* __restrict__ cl)
{
    int idx = blockIdx.x * 256 + threadIdx.x;   // float4 over 4096*256
    int row = idx >> 8, c = idx & 255;
    float4 v = ((const float4*)desc)[idx];
    uint32_t h0, l0, h1, l1;
    split2(v.x, v.y, h0, l0);
    split2(v.z, v.w, h1, l1);
    ((uint2*)ch)[(size_t)row * 512 + c] = make_uint2(h0, h1);
    ((uint2*)cl)[(size_t)row * 512 + c] = make_uint2(l0, l1);
}

// ============================================================================
// HMMA GEMM on pre-split bf16 operands, 3-stage cp.async pipeline.
// C[M,n] = (Ah+Al)[M,K] @ (Wh+Wl)[n,K]^T + bias (+res) ; 3-pass split product.
// grid (n/128, M/128), block 256. Stage = 32KB ([A 16K][W 16K], rows 128B
// = [32 hi bf16 | 32 lo bf16], SW128 swizzle). Dynamic smem 96KB.
// ============================================================================
__global__ void __launch_bounds__(256) gemm_bf(
    const __nv_bfloat16* __restrict__ Ah, const __nv_bfloat16* __restrict__ Al, int lda,
    const __nv_bfloat16* __restrict__ Wh, const __nv_bfloat16* __restrict__ Wl,
    const float* __restrict__ bias, const float* __restrict__ res,
    float* __restrict__ Cf, uint32_t* __restrict__ Chi, uint32_t* __restrict__ Clo,
    int ldc, int K)
{
    extern __shared__ __align__(1024) char smem[];
    const uint32_t sb = smem_u32(smem);
    const int NC = K >> 5;
    const int tid = threadIdx.x;
    const int lane = tid & 31, wid = tid >> 5;
    const int wm = wid >> 2, wn = wid & 3;
    const int m0 = blockIdx.y * 128, n0 = blockIdx.x * 128;
    const int lr = tid >> 2, seg = tid & 3;

    auto load_stage = [&](int c) {
        const int kc = c << 5;
        const uint32_t base = sb + (c % 3) * 32768;
#pragma unroll
        for (int i = 0; i < 2; i++) {
            int rr = lr + i * 64;
            uint32_t oh = base + sw128((uint32_t)(rr * 128 + seg * 16));
            uint32_t ol = base + sw128((uint32_t)(rr * 128 + 64 + seg * 16));
            const __nv_bfloat16* pa  = Ah + (size_t)(m0 + rr) * lda + kc + seg * 8;
            const __nv_bfloat16* pal = Al + (size_t)(m0 + rr) * lda + kc + seg * 8;
            const __nv_bfloat16* pw  = Wh + (size_t)(n0 + rr) * K + kc + seg * 8;
            const __nv_bfloat16* pwl = Wl + (size_t)(n0 + rr) * K + kc + seg * 8;
            CP16(oh, pa);
            CP16(ol, pal);
            CP16(oh + 16384, pw);
            CP16(ol + 16384, pwl);
        }
        CPCOMMIT();
    };

    load_stage(0);
    load_stage(1);

    float acc[4][4][4];
#pragma unroll
    for (int mt = 0; mt < 4; mt++)
#pragma unroll
        for (int nt = 0; nt < 4; nt++)
#pragma unroll
            for (int e = 0; e < 4; e++) acc[mt][nt][e] = 0.f;

    const int lrow = (lane & 7) + ((lane >> 3) & 1) * 8;
    const int lkh = ((lane >> 4) & 1) * 8;

    for (int c = 0; c < NC; c++) {
        CPWAIT1();
        __syncthreads();
        if (c + 2 < NC) load_stage(c + 2);

        const uint32_t ab = sb + (c % 3) * 32768;
        const uint32_t bbs = ab + 16384;
#pragma unroll
        for (int s = 0; s < 2; s++) {
            const int kh = s * 16 + lkh;
            uint32_t ah4[4][4], al4[4][4];
#pragma unroll
            for (int mt = 0; mt < 4; mt++) {
                uint32_t row = (uint32_t)(wm * 64 + mt * 16 + lrow);
                uint32_t offh = row * 128 + kh * 2;
                ldsm4(ab + sw128(offh), ah4[mt]);
                ldsm4(ab + sw128(offh + 64), al4[mt]);
            }
            uint32_t bh4[2][4], bl4[2][4];
#pragma unroll
            for (int p = 0; p < 2; p++) {
                uint32_t row = (uint32_t)(wn * 32 + p * 16 + lrow);
                uint32_t offh = row * 128 + kh * 2;
                ldsm4(bbs + sw128(offh), bh4[p]);
                ldsm4(bbs + sw128(offh + 64), bl4[p]);
            }
#pragma unroll
            for (int mt = 0; mt < 4; mt++) {
#pragma unroll
                for (int nt = 0; nt < 4; nt++) {
                    int p = nt >> 1, q = nt & 1;
                    mma16816(acc[mt][nt], ah4[mt], bh4[p][q], bh4[p][q + 2]);
                    mma16816(acc[mt][nt], ah4[mt], bl4[p][q], bl4[p][q + 2]);
                    mma16816(acc[mt][nt], al4[mt], bh4[p][q], bh4[p][q + 2]);
                }
            }
        }
    }

    // ---- epilogue
    const int g = lane >> 2, tg = lane & 3;
#pragma unroll
    for (int mt = 0; mt < 4; mt++) {
#pragma unroll
        for (int nt = 0; nt < 4; nt++) {
            int row = m0 + wm * 64 + mt * 16 + g;
            int col = n0 + wn * 32 + nt * 8 + 2 * tg;
            float2 bv = *(const float2*)&bias[col];
            float2 v0 = make_float2(acc[mt][nt][0] + bv.x, acc[mt][nt][1] + bv.y);
            float2 v1 = make_float2(acc[mt][nt][2] + bv.x, acc[mt][nt][3] + bv.y);
            if (res) {
                float2 r0 = *(const float2*)&res[(size_t)row * ldc + col];
                float2 r1 = *(const float2*)&res[(size_t)(row + 8) * ldc + col];
                v0.x += r0.x; v0.y += r0.y; v1.x += r1.x; v1.y += r1.y;
            }
            if (Cf) {
                *(float2*)&Cf[(size_t)row * ldc + col] = v0;
                *(float2*)&Cf[(size_t)(row + 8) * ldc + col] = v1;
            }
            if (Chi) {
                uint32_t h0, l0, h1, l1;
                split2(v0.x, v0.y, h0, l0);
                split2(v1.x, v1.y, h1, l1);
                size_t i0 = ((size_t)row * ldc + col) >> 1;
                size_t i1 = ((size_t)(row + 8) * ldc + col) >> 1;
                Chi[i0] = h0; Clo[i0] = l0;
                Chi[i1] = h1; Clo[i1] = l1;
            }
        }
    }
}

// ============================================================================
// rope + deinterleave; writes pre-split bf16 q (pre-scaled), k, v
// one thread per (b,h,n,d-pair)
// ============================================================================
__global__ void __launch_bounds__(256) rope_split(
    const float* __restrict__ qkv, const float* __restrict__ enc,
    uint32_t* __restrict__ qh, uint32_t* __restrict__ ql,
    uint32_t* __restrict__ kh, uint32_t* __restrict__ kl,
    uint32_t* __restrict__ vh, uint32_t* __restrict__ vl)
{
    int i2 = blockIdx.x * 256 + threadIdx.x;
    if (i2 >= EHALF / 2) return;
    int d2 = i2 & 31;
    int n  = (i2 >> 5) & 2047;
    int h  = (i2 >> 16) & 15;
    int b  = i2 >> 20;

    float2 e0 = *(const float2*)&enc[(size_t)2 * i2];
    float2 e1 = *(const float2*)&enc[(size_t)EHALF + 2 * i2];

    size_t rowb = (size_t)(b * NN_SEQ + n) * (3 * DD);
    int c0 = (h * HD + 2 * d2) * 3;
    float2 a  = *(const float2*)&qkv[rowb + c0];       // q0, k0
    float2 bb = *(const float2*)&qkv[rowb + c0 + 2];   // v0, q1
    float2 cc = *(const float2*)&qkv[rowb + c0 + 4];   // k1, v1

    float q0 = a.x, k0 = a.y, v0 = bb.x, q1 = bb.y, k1 = cc.x, v1 = cc.y;
    float qr0 = (q0 * e0.x - q1 * e1.x) * 0.125f;
    float qr1 = (q1 * e0.y + q0 * e1.y) * 0.125f;
    float kr0 = k0 * e0.x - k1 * e1.x;
    float kr1 = k1 * e0.y + k0 * e1.y;

    uint32_t hh, ll;
    split2(qr0, qr1, hh, ll); qh[i2] = hh; ql[i2] = ll;
    split2(kr0, kr1, hh, ll); kh[i2] = hh; kl[i2] = ll;
    split2(v0,  v1,  hh, ll); vh[i2] = hh; vl[i2] = ll;
}

// ============================================================================
// HMMA flash attention on pre-split bf16 Q/K/V, 2-stage cp.async KV pipeline.
// grid (N/128, B*H), block 256. Dynamic smem 64KB.
// Stage layout (32KB): [Khi 8K][Klo 8K][Vhi 8K][Vlo 8K], rows 128B, SW128.
// Writes ctx split (hi/lo bf16) in [B,N,D] layout.
// ============================================================================
__global__ void __launch_bounds__(256) attn_bf(
    const __nv_bfloat16* __restrict__ Qh, const __nv_bfloat16* __restrict__ Ql,
    const __nv_bfloat16* __restrict__ Kh, const __nv_bfloat16* __restrict__ Kl,
    const __nv_bfloat16* __restrict__ Vh, const __nv_bfloat16* __restrict__ Vl,
    uint32_t* __restrict__ ctxh, uint32_t* __restrict__ ctxl)
{
    extern __shared__ __align__(1024) char sm[];
    const uint32_t sb = smem_u32(sm);
    const int tid = threadIdx.x;
    const int lane = tid & 31, wid = tid >> 5;
    const int bh = blockIdx.y;
    const int q0 = blockIdx.x * 128;
    const int b = bh >> 4, h = bh & 15;

    const __nv_bfloat16* Qbh = Qh + ((size_t)bh * NN_SEQ + q0) * HD;
    const __nv_bfloat16* Qbl = Ql + ((size_t)bh * NN_SEQ + q0) * HD;
    const __nv_bfloat16* Kbh = Kh + (size_t)bh * NN_SEQ * HD;
    const __nv_bfloat16* Kbl = Kl + (size_t)bh * NN_SEQ * HD;
    const __nv_bfloat16* Vbh = Vh + (size_t)bh * NN_SEQ * HD;
    const __nv_bfloat16* Vbl = Vl + (size_t)bh * NN_SEQ * HD;

    // ---- stage Q (hi at 0, lo at 16K), extract fragments
#pragma unroll
    for (int i = 0; i < 4; i++) {
        int f = tid + i * 256;
        int r = f >> 3, seg = f & 7;
        uint32_t off = sw128((uint32_t)(r * 128 + seg * 16));
        CP16(sb + off,         Qbh + (size_t)r * HD + seg * 8);
        CP16(sb + 16384 + off, Qbl + (size_t)r * HD + seg * 8);
    }
    CPCOMMIT();
    CPWAIT0();
    __syncthreads();

    const int lrow = (lane & 7) + ((lane >> 3) & 1) * 8;
    const int lkh16 = ((lane >> 4) & 1) * 16;
    uint32_t qh4[4][4], ql4[4][4];
#pragma unroll
    for (int kc = 0; kc < 4; kc++) {
        uint32_t row = (uint32_t)(wid * 16 + lrow);
        uint32_t off = row * 128 + kc * 32 + lkh16;
        ldsm4(sb + sw128(off), qh4[kc]);
        ldsm4(sb + 16384 + sw128(off), ql4[kc]);
    }
    __syncthreads();

    auto load_kv = [&](int t) {
        const int kv0 = t * 64;
        const uint32_t base = sb + (t & 1) * 32768;
#pragma unroll
        for (int i = 0; i < 2; i++) {
            int f = tid + i * 256;
            int r = f >> 3, seg = f & 7;
            uint32_t off = sw128((uint32_t)(r * 128 + seg * 16));
            size_t g = (size_t)(kv0 + r) * HD + seg * 8;
            CP16(base + off,         Kbh + g);
            CP16(base + 8192 + off,  Kbl + g);
            CP16(base + 16384 + off, Vbh + g);
            CP16(base + 24576 + off, Vbl + g);
        }
        CPCOMMIT();
    };
    load_kv(0);

    float m_i[2], l_i[2], o[8][4];
    m_i[0] = m_i[1] = -1e30f;
    l_i[0] = l_i[1] = 0.f;
#pragma unroll
    for (int nt = 0; nt < 8; nt++)
#pragma unroll
        for (int e = 0; e < 4; e++) o[nt][e] = 0.f;

    const int vtile = lane >> 3, vri = lane & 7;

    for (int t = 0; t < NN_SEQ / 64; t++) {
        CPWAIT0();
        __syncthreads();
        if (t + 1 < NN_SEQ / 64) load_kv(t + 1);

        const uint32_t kb = sb + (t & 1) * 32768;

        // ---- S = Q K^T
        float s[8][4];
#pragma unroll
        for (int nt = 0; nt < 8; nt++)
#pragma unroll
            for (int e = 0; e < 4; e++) s[nt][e] = 0.f;

#pragma unroll
        for (int kc = 0; kc < 4; kc++) {
            uint32_t kh4[4][4], kl4[4][4];
#pragma unroll
            for (int p = 0; p < 4; p++) {
                uint32_t row = (uint32_t)(p * 16 + lrow);
                uint32_t off = row * 128 + kc * 32 + lkh16;
                ldsm4(kb + sw128(off), kh4[p]);
                ldsm4(kb + 8192 + sw128(off), kl4[p]);
            }
#pragma unroll
            for (int nt = 0; nt < 8; nt++) {
                int p = nt >> 1, q = nt & 1;
                mma16816(s[nt], qh4[kc], kh4[p][q], kh4[p][q + 2]);
                mma16816(s[nt], qh4[kc], kl4[p][q], kl4[p][q + 2]);
                mma16816(s[nt], ql4[kc], kh4[p][q], kh4[p][q + 2]);
            }
        }

        // ---- online softmax (rows g, g+8; quad lanes share a row)
#pragma unroll
        for (int i = 0; i < 2; i++) {
            float mx = -1e30f;
#pragma unroll
            for (int nt = 0; nt < 8; nt++)
                mx = fmaxf(mx, fmaxf(s[nt][2 * i], s[nt][2 * i + 1]));
            mx = fmaxf(mx, __shfl_xor_sync(0xffffffffu, mx, 1));
            mx = fmaxf(mx, __shfl_xor_sync(0xffffffffu, mx, 2));
            float mn = fmaxf(m_i[i], mx);
            float alpha = __expf(m_i[i] - mn);
            m_i[i] = mn;
            float rs = 0.f;
#pragma unroll
            for (int nt = 0; nt < 8; nt++) {
                float p0 = __expf(s[nt][2 * i]     - mn);
                float p1 = __expf(s[nt][2 * i + 1] - mn);
                s[nt][2 * i] = p0; s[nt][2 * i + 1] = p1;
                rs += p0 + p1;
            }
            rs += __shfl_xor_sync(0xffffffffu, rs, 1);
            rs += __shfl_xor_sync(0xffffffffu, rs, 2);
            l_i[i] = l_i[i] * alpha + rs;
#pragma unroll
            for (int nt = 0; nt < 8; nt++) {
                o[nt][2 * i]     *= alpha;
                o[nt][2 * i + 1] *= alpha;
            }
        }

        // ---- pack P into split A fragments
        uint32_t ph[4][4], pl[4][4];
#pragma unroll
        for (int j = 0; j < 4; j++) {
            split2(s[2 * j][0],     s[2 * j][1],     ph[j][0], pl[j][0]);
            split2(s[2 * j][2],     s[2 * j][3],     ph[j][1], pl[j][1]);
            split2(s[2 * j + 1][0], s[2 * j + 1][1], ph[j][2], pl[j][2]);
            split2(s[2 * j + 1][2], s[2 * j + 1][3], ph[j][3], pl[j][3]);
        }

        // ---- O += P V
#pragma unroll
        for (int j = 0; j < 4; j++) {
            uint32_t kvr = (uint32_t)(j * 16 + (vtile & 1) * 8 + vri);
            uint32_t wh4[4][4], wl4[4][4];
#pragma unroll
            for (int t4 = 0; t4 < 4; t4++) {
                uint32_t off = kvr * 128 + (t4 * 16 + (vtile >> 1) * 8) * 2;
                ldsm4t(kb + 16384 + sw128(off), wh4[t4]);
                ldsm4t(kb + 24576 + sw128(off), wl4[t4]);
            }
#pragma unroll
            for (int nt = 0; nt < 8; nt++) {
                int t4 = nt >> 1, hh2 = nt & 1;
                uint32_t b0h = wh4[t4][hh2 * 2], b1h = wh4[t4][hh2 * 2 + 1];
                uint32_t b0l = wl4[t4][hh2 * 2], b1l = wl4[t4][hh2 * 2 + 1];
                mma16816(o[nt], ph[j], b0h, b1h);
                mma16816(o[nt], ph[j], b0l, b1l);
                mma16816(o[nt], pl[j], b0h, b1h);
            }
        }
    }

    // ---- epilogue: normalize, split, write ctx[b][n][h*64+d]
    const int g = lane >> 2, tg = lane & 3;
#pragma unroll
    for (int i = 0; i < 2; i++) {
        float inv = 1.f / l_i[i];
        int n = q0 + wid * 16 + g + i * 8;
        size_t base = (size_t)(b * NN_SEQ + n) * (DD / 2) + h * (HD / 2);
#pragma unroll
        for (int nt = 0; nt < 8; nt++) {
            uint32_t hh, ll;
            split2(o[nt][2 * i] * inv, o[nt][2 * i + 1] * inv, hh, ll);
            size_t idx = base + ((nt * 8 + 2 * tg) >> 1);
            ctxh[idx] = hh;
            ctxl[idx] = ll;
        }
    }
}

// ---------------- LayerNorm + exact GELU -> split bf16 ---------------------
__global__ void __launch_bounds__(256) ln_gelu_kernel(
    const float* __restrict__ H, const float* __restrict__ g,
    const float* __restrict__ bta,
    uint32_t* __restrict__ hh, uint32_t* __restrict__ hl)
{
    __shared__ float rs[8], rq[8], stat[2];
    const float* hr = H + (size_t)blockIdx.x * 2048;
    const int tid = threadIdx.x;

    float4 x[2];
    float sum = 0.f, sq = 0.f;
#pragma unroll
    for (int t = 0; t < 2; t++) {
        x[t] = *(const float4*)&hr[(tid + t * 256) * 4];
        sum += x[t].x + x[t].y + x[t].z + x[t].w;
        sq  += x[t].x * x[t].x + x[t].y * x[t].y + x[t].z * x[t].z + x[t].w * x[t].w;
    }
#pragma unroll
    for (int off = 16; off > 0; off >>= 1) {
        sum += __shfl_xor_sync(0xffffffffu, sum, off);
        sq  += __shfl_xor_sync(0xffffffffu, sq,  off);
    }
    int w = tid >> 5, lane = tid & 31;
    if (!lane) { rs[w] = sum; rq[w] = sq; }
    __syncthreads();
    if (tid == 0) {
        float S = 0.f, Q = 0.f;
#pragma unroll
        for (int i = 0; i < 8; i++) { S += rs[i]; Q += rq[i]; }
        float mu = S * (1.f / 2048.f);
        float var = Q * (1.f / 2048.f) - mu * mu;
        stat[0] = mu;
        stat[1] = rsqrtf(var + 1e-5f);
    }
    __syncthreads();
    float mu = stat[0], rstd = stat[1];

#pragma unroll
    for (int t = 0; t < 2; t++) {
        int c0 = (tid + t * 256) * 4;
        float4 gg = *(const float4*)&g[c0];
        float4 bb = *(const float4*)&bta[c0];
        float xs[4] = {x[t].x, x[t].y, x[t].z, x[t].w};
        float gs[4] = {gg.x, gg.y, gg.z, gg.w};
        float bs[4] = {bb.x, bb.y, bb.z, bb.w};
        float ys[4];
#pragma unroll
        for (int j = 0; j < 4; j++) {
            float xn = (xs[j] - mu) * rstd * gs[j] + bs[j];
            ys[j] = 0.5f * xn * (1.f + erff(xn * 0.70710678118654752f));
        }
        uint32_t h0, l0, h1, l1;
        split2(ys[0], ys[1], h0, l0);
        split2(ys[2], ys[3], h1, l1);
        size_t i2 = ((size_t)blockIdx.x * 2048 + c0) >> 2;
        ((uint2*)hh)[i2] = make_uint2(h0, h1);
        ((uint2*)hl)[i2] = make_uint2(l0, l1);
    }
}

// ---------------- launch ----------------------------------------------------
extern "C" void kernel_launch(void* const* d_in, const int* in_sizes, int n_in,
                              void* d_out, int out_size)
{
    const float* desc   = (const float*)d_in[0];
    const float* enc    = (const float*)d_in[1];
    const float* w_qkv  = (const float*)d_in[2];
    const float* b_qkv  = (const float*)d_in[3];
    const float* w_out  = (const float*)d_in[4];
    const float* b_out  = (const float*)d_in[5];
    const float* w_ffn1 = (const float*)d_in[6];
    const float* b_ffn1 = (const float*)d_in[7];
    const float* ln_g   = (const float*)d_in[8];
    const float* ln_b   = (const float*)d_in[9];
    const float* w_ffn2 = (const float*)d_in[10];
    const float* b_ffn2 = (const float*)d_in[11];
    float* out = (float*)d_out;

    float *p_qkv, *p_h;
    uint32_t *p_qh, *p_ql, *p_kh, *p_kl, *p_vh, *p_vl;
    uint32_t *p_ctxh, *p_ctxl, *p_cath, *p_catl, *p_hh, *p_hl;
    uint32_t *p_wqkvh, *p_wqkvl, *p_wouth, *p_woutl, *p_wf1h, *p_wf1l, *p_wf2h, *p_wf2l;
    cudaGetSymbolAddress((void**)&p_qkv,  g_qkv);
    cudaGetSymbolAddress((void**)&p_h,    g_h);
    cudaGetSymbolAddress((void**)&p_qh,   g_qh);
    cudaGetSymbolAddress((void**)&p_ql,   g_ql);
    cudaGetSymbolAddress((void**)&p_kh,   g_kh);
    cudaGetSymbolAddress((void**)&p_kl,   g_kl);
    cudaGetSymbolAddress((void**)&p_vh,   g_vh);
    cudaGetSymbolAddress((void**)&p_vl,   g_vl);
    cudaGetSymbolAddress((void**)&p_ctxh, g_ctxh);
    cudaGetSymbolAddress((void**)&p_ctxl, g_ctxl);
    cudaGetSymbolAddress((void**)&p_cath, g_cath);
    cudaGetSymbolAddress((void**)&p_catl, g_catl);
    cudaGetSymbolAddress((void**)&p_hh,   g_hh);
    cudaGetSymbolAddress((void**)&p_hl,   g_hl);
    cudaGetSymbolAddress((void**)&p_wqkvh, g_wqkvh);
    cudaGetSymbolAddress((void**)&p_wqkvl, g_wqkvl);
    cudaGetSymbolAddress((void**)&p_wouth, g_wouth);
    cudaGetSymbolAddress((void**)&p_woutl, g_woutl);
    cudaGetSymbolAddress((void**)&p_wf1h,  g_wf1h);
    cudaGetSymbolAddress((void**)&p_wf1l,  g_wf1l);
    cudaGetSymbolAddress((void**)&p_wf2h,  g_wf2h);
    cudaGetSymbolAddress((void**)&p_wf2l,  g_wf2l);

    cudaFuncSetAttribute(gemm_bf, cudaFuncAttributeMaxDynamicSharedMemorySize, 98304);
    cudaFuncSetAttribute(attn_bf, cudaFuncAttributeMaxDynamicSharedMemorySize, 65536);

    // 0. split weights + descriptor (descriptor lands in cat[:, :1024])
    wsplit<<<3 * DD * DD / 4 / 256, 256>>>(w_qkv, p_wqkvh, p_wqkvl, 3 * DD * DD / 4);
    wsplit<<<DD * DD / 4 / 256, 256>>>(w_out, p_wouth, p_woutl, DD * DD / 4);
    wsplit<<<4 * DD * DD / 256, 256>>>(w_ffn1, p_wf1h, p_wf1l, DD * DD);
    wsplit<<<2 * DD * DD / 4 / 256, 256>>>(w_ffn2, p_wf2h, p_wf2l, 2 * DD * DD / 4);
    desc_split<<<ROWS * 256 / 256, 256>>>(desc, p_cath, p_catl);

    // 1. QKV projection (A = desc via cat with lda=2048)
    gemm_bf<<<dim3(3072 / 128, ROWS / 128), 256, 98304>>>(
        (const __nv_bfloat16*)p_cath, (const __nv_bfloat16*)p_catl, 2048,
        (const __nv_bfloat16*)p_wqkvh, (const __nv_bfloat16*)p_wqkvl,
        b_qkv, nullptr, p_qkv, nullptr, nullptr, 3072, 1024);

    // 2. rope + deinterleave + split (q pre-scaled)
    rope_split<<<EHALF / 2 / 256, 256>>>(p_qkv, enc, p_qh, p_ql, p_kh, p_kl, p_vh, p_vl);

    // 3. attention -> ctx split
    attn_bf<<<dim3(NN_SEQ / 128, BB * HH), 256, 65536>>>(
        (const __nv_bfloat16*)p_qh, (const __nv_bfloat16*)p_ql,
        (const __nv_bfloat16*)p_kh, (const __nv_bfloat16*)p_kl,
        (const __nv_bfloat16*)p_vh, (const __nv_bfloat16*)p_vl,
        p_ctxh, p_ctxl);

    // 4. output projection -> split message into cat[:, 1024:]
    gemm_bf<<<dim3(1024 / 128, ROWS / 128), 256, 98304>>>(
        (const __nv_bfloat16*)p_ctxh, (const __nv_bfloat16*)p_ctxl, 1024,
        (const __nv_bfloat16*)p_wouth, (const __nv_bfloat16*)p_woutl,
        b_out, nullptr, nullptr, p_cath + 512, p_catl + 512, 2048, 1024);

    // 5. FFN1 -> h fp32
    gemm_bf<<<dim3(2048 / 128, ROWS / 128), 256, 98304>>>(
        (const __nv_bfloat16*)p_cath, (const __nv_bfloat16*)p_catl, 2048,
        (const __nv_bfloat16*)p_wf1h, (const __nv_bfloat16*)p_wf1l,
        b_ffn1, nullptr, p_h, nullptr, nullptr, 2048, 2048);

    // 6. LayerNorm + GELU -> split h
    ln_gelu_kernel<<<ROWS, 256>>>(p_h, ln_g, ln_b, p_hh, p_hl);

    // 7. FFN2 + residual -> out (fp32)
    gemm_bf<<<dim3(1024 / 128, ROWS / 128), 256, 98304>>>(
        (const __nv_bfloat16*)p_hh, (const __nv_bfloat16*)p_hl, 2048,
        (const __nv_bfloat16*)p_wf2h, (const __nv_bfloat16*)p_wf2l,
        b_ffn2, desc, out, nullptr, nullptr, 1024, 2048);
}